// round 11
// baseline (speedup 1.0000x reference)
#include <cuda_runtime.h>
#include <cstdint>

#define BATCH 16
#define SEQ   4096
#define CH    512
#define DIM   64

// Scratch (allocation-free per harness rules)
__device__ float g_qh[BATCH * SEQ * DIM];
__device__ float g_ql[BATCH * SEQ * DIM];
__device__ float g_k [BATCH * SEQ * DIM];
__device__ float g_kTh[BATCH * DIM * SEQ];   // [b, d, n] hi
__device__ float g_kTl[BATCH * DIM * SEQ];   // [b, d, n] lo
__device__ float g_v [BATCH * SEQ * CH];

// ===========================================================================
// helpers
// ===========================================================================
__device__ __forceinline__ uint32_t smem_u32(const void* p) {
    uint32_t a;
    asm("{ .reg .u64 t; cvta.to.shared.u64 t, %1; cvt.u32.u64 %0, t; }" : "=r"(a) : "l"(p));
    return a;
}
__device__ __forceinline__ float tf32r(float x) {
    uint32_t r;
    asm("cvt.rna.tf32.f32 %0, %1;" : "=r"(r) : "f"(x));
    return __uint_as_float(r);
}
__device__ __forceinline__ void cp16(uint32_t dst, const void* src) {
    asm volatile("cp.async.cg.shared.global [%0], [%1], 16;" :: "r"(dst), "l"(src));
}
#define CP_COMMIT() asm volatile("cp.async.commit_group;" ::: "memory")
#define CP_WAIT_2() asm volatile("cp.async.wait_group 2;" ::: "memory")
#define CP_WAIT_1() asm volatile("cp.async.wait_group 1;" ::: "memory")
#define CP_WAIT_0() asm volatile("cp.async.wait_group 0;" ::: "memory")

#define MMA_TF32(c, a0, a1, a2, a3, b0, b1) \
    asm volatile( \
        "mma.sync.aligned.m16n8k8.row.col.f32.tf32.tf32.f32 " \
        "{%0,%1,%2,%3}, {%4,%5,%6,%7}, {%8,%9}, {%0,%1,%2,%3};" \
        : "+f"((c)[0]), "+f"((c)[1]), "+f"((c)[2]), "+f"((c)[3]) \
        : "r"(a0), "r"(a1), "r"(a2), "r"(a3), "r"(b0), "r"(b1))

// ===========================================================================
// proj: C[M,N] = A[M,512] @ W[512,N] + bias.
// round_out=1: store tf32-rounded.  C_lo != null: store Dekker hi/lo pair.
// ===========================================================================
__global__ __launch_bounds__(256, 2)
void proj_kernel(const float* __restrict__ A, const float* __restrict__ W,
                 const float* __restrict__ bias, float* __restrict__ C,
                 float* __restrict__ C_lo, int N, int round_out) {
    const int K = CH;
    __shared__ float As[32][132];
    __shared__ float Ws[32][64];
    const int bm = blockIdx.y * 128;
    const int bn = blockIdx.x * 64;
    const int tid = threadIdx.x;
    const int tn = tid & 15;
    const int tm = tid >> 4;
    float acc[8][4] = {};

    for (int k0 = 0; k0 < K; k0 += 32) {
        #pragma unroll
        for (int i = 0; i < 4; i++) {
            int fidx = tid + i * 256;
            int row  = fidx >> 3;
            int kc   = (fidx & 7) * 4;
            float4 t = *(const float4*)(A + (size_t)(bm + row) * K + k0 + kc);
            As[kc + 0][row] = t.x; As[kc + 1][row] = t.y;
            As[kc + 2][row] = t.z; As[kc + 3][row] = t.w;
        }
        #pragma unroll
        for (int i = 0; i < 2; i++) {
            int fidx = tid + i * 256;
            int kr   = fidx >> 4;
            int nc   = (fidx & 15) * 4;
            *(float4*)&Ws[kr][nc] = *(const float4*)(W + (size_t)(k0 + kr) * N + bn + nc);
        }
        __syncthreads();
        #pragma unroll
        for (int kk = 0; kk < 32; kk++) {
            float4 a0 = *(const float4*)&As[kk][tm * 8];
            float4 a1 = *(const float4*)&As[kk][tm * 8 + 4];
            float4 w0 = *(const float4*)&Ws[kk][tn * 4];
            float a[8] = {a0.x, a0.y, a0.z, a0.w, a1.x, a1.y, a1.z, a1.w};
            float w[4] = {w0.x, w0.y, w0.z, w0.w};
            #pragma unroll
            for (int i = 0; i < 8; i++)
                #pragma unroll
                for (int j = 0; j < 4; j++)
                    acc[i][j] = fmaf(a[i], w[j], acc[i][j]);
        }
        __syncthreads();
    }
    #pragma unroll
    for (int i = 0; i < 8; i++) {
        size_t row = bm + tm * 8 + i;
        int col = bn + tn * 4;
        float4 o;
        o.x = acc[i][0] + bias[col + 0];
        o.y = acc[i][1] + bias[col + 1];
        o.z = acc[i][2] + bias[col + 2];
        o.w = acc[i][3] + bias[col + 3];
        if (C_lo) {
            float4 h, l;
            h.x = tf32r(o.x); l.x = tf32r(o.x - h.x);
            h.y = tf32r(o.y); l.y = tf32r(o.y - h.y);
            h.z = tf32r(o.z); l.z = tf32r(o.z - h.z);
            h.w = tf32r(o.w); l.w = tf32r(o.w - h.w);
            *(float4*)(C    + row * N + col) = h;
            *(float4*)(C_lo + row * N + col) = l;
        } else {
            if (round_out) {
                o.x = tf32r(o.x); o.y = tf32r(o.y);
                o.z = tf32r(o.z); o.w = tf32r(o.w);
            }
            *(float4*)(C + row * N + col) = o;
        }
    }
}

// ===========================================================================
// ksplit: k[b,n,d] -> kT_hi/kT_lo [b,d,n]  (transpose + Dekker split)
// ===========================================================================
__global__ __launch_bounds__(256)
void ksplit_kernel(const float* __restrict__ K, float* __restrict__ KTh,
                   float* __restrict__ KTl) {
    __shared__ float t[32][33];
    const int b  = blockIdx.z;
    const int d0 = blockIdx.x * 32;
    const int n0 = blockIdx.y * 32;
    const float* Kb = K + (size_t)b * SEQ * DIM;
    const size_t tb = (size_t)b * DIM * SEQ;
    const int tx = threadIdx.x, ty = threadIdx.y;
    #pragma unroll
    for (int j = 0; j < 4; j++)
        t[ty + j * 8][tx] = Kb[(size_t)(n0 + ty + j * 8) * DIM + d0 + tx];
    __syncthreads();
    #pragma unroll
    for (int j = 0; j < 4; j++) {
        float v = t[tx][ty + j * 8];
        float h = tf32r(v);
        size_t off = tb + (size_t)(d0 + ty + j * 8) * SEQ + n0 + tx;
        KTh[off] = h;
        KTl[off] = tf32r(v - h);
    }
}

// ===========================================================================
// energy_mma: E[b,m,n] = QK^T on tensor cores, pre-split hi/lo operands.
// CTA tile 128m x 128n (two 64n subtiles). A hi/lo resident; K double-buffered.
// 8 warps of 64m x 16n per subtile. No cvt in hot loop.
// ===========================================================================
#define EAH_OFF 0
#define EAL_OFF 8704                       // 128*68
#define EKB(b)  (17408 + (b) * 9216)       // K hi; K lo = +4608 (64*72)
#define E_SMEM_F 35840
#define E_SMEM_BYTES (E_SMEM_F * 4)        // 143360

__global__ __launch_bounds__(256, 1)
void energy_mma_kernel(const float* __restrict__ Qh, const float* __restrict__ Ql,
                       const float* __restrict__ KTh, const float* __restrict__ KTl,
                       float* __restrict__ E) {
    extern __shared__ float smemf[];
    uint32_t sb = smem_u32(smemf);

    const int tid  = threadIdx.x;
    const int wid  = tid >> 5;
    const int lane = tid & 31;
    const int gid  = lane >> 2;      // 0..7
    const int tig  = lane & 3;       // 0..3
    const int wm   = (wid >> 2) * 64;    // 0 or 64
    const int wn   = (wid & 3) * 16;     // 0,16,32,48

    const int bz = blockIdx.z;
    const int bm = blockIdx.y * 128;
    const int bn = blockIdx.x * 128;
    const float* Qhb = Qh + ((size_t)bz * SEQ + bm) * DIM;
    const float* Qlb = Ql + ((size_t)bz * SEQ + bm) * DIM;
    const float* KThb = KTh + (size_t)bz * DIM * SEQ;
    const float* KTlb = KTl + (size_t)bz * DIM * SEQ;
    float* Eb = E + (size_t)bz * SEQ * SEQ;

    // A hi/lo (128x64, stride 68) + K subtile 0, then K subtile 1
    #pragma unroll
    for (int j = 0; j < 8; j++) {
        int idx = tid + j * 256;     // 0..2047
        int r   = idx >> 4;          // 0..127
        int c   = idx & 15;
        cp16(sb + (uint32_t)(EAH_OFF + r * 68 + c * 4) * 4, Qhb + (size_t)r * DIM + c * 4);
        cp16(sb + (uint32_t)(EAL_OFF + r * 68 + c * 4) * 4, Qlb + (size_t)r * DIM + c * 4);
    }
    #pragma unroll
    for (int j = 0; j < 4; j++) {
        int idx = tid + j * 256;     // 0..1023
        int d   = idx >> 4;          // 0..63
        int c   = idx & 15;
        cp16(sb + (uint32_t)(EKB(0) + d * 72 + c * 4) * 4,        KThb + (size_t)d * SEQ + bn + c * 4);
        cp16(sb + (uint32_t)(EKB(0) + 4608 + d * 72 + c * 4) * 4, KTlb + (size_t)d * SEQ + bn + c * 4);
    }
    CP_COMMIT();
    #pragma unroll
    for (int j = 0; j < 4; j++) {
        int idx = tid + j * 256;
        int d   = idx >> 4;
        int c   = idx & 15;
        cp16(sb + (uint32_t)(EKB(1) + d * 72 + c * 4) * 4,        KThb + (size_t)d * SEQ + bn + 64 + c * 4);
        cp16(sb + (uint32_t)(EKB(1) + 4608 + d * 72 + c * 4) * 4, KTlb + (size_t)d * SEQ + bn + 64 + c * 4);
    }
    CP_COMMIT();

    const float* AH = smemf + EAH_OFF;
    const float* AL = smemf + EAL_OFF;

    #pragma unroll
    for (int sub = 0; sub < 2; sub++) {
        if (sub == 0) { CP_WAIT_1(); } else { CP_WAIT_0(); }
        __syncthreads();
        const float* KH = smemf + EKB(sub);
        const float* KL = KH + 4608;

        float acc[8][4];
        #pragma unroll
        for (int i = 0; i < 8; i++)
            #pragma unroll
            for (int j = 0; j < 4; j++) acc[i][j] = 0.f;

        #pragma unroll
        for (int kk = 0; kk < 64; kk += 8) {
            uint32_t ah[4][4], al[4][4], bh[2][2], bl[2][2];
            #pragma unroll
            for (int mt = 0; mt < 4; mt++) {
                int r = wm + mt * 16 + gid;
                ah[mt][0] = __float_as_uint(AH[r * 68 + kk + tig]);
                ah[mt][1] = __float_as_uint(AH[(r + 8) * 68 + kk + tig]);
                ah[mt][2] = __float_as_uint(AH[r * 68 + kk + tig + 4]);
                ah[mt][3] = __float_as_uint(AH[(r + 8) * 68 + kk + tig + 4]);
                al[mt][0] = __float_as_uint(AL[r * 68 + kk + tig]);
                al[mt][1] = __float_as_uint(AL[(r + 8) * 68 + kk + tig]);
                al[mt][2] = __float_as_uint(AL[r * 68 + kk + tig + 4]);
                al[mt][3] = __float_as_uint(AL[(r + 8) * 68 + kk + tig + 4]);
            }
            #pragma unroll
            for (int nt = 0; nt < 2; nt++) {
                int n = wn + nt * 8 + gid;
                bh[nt][0] = __float_as_uint(KH[(kk + tig) * 72 + n]);
                bh[nt][1] = __float_as_uint(KH[(kk + tig + 4) * 72 + n]);
                bl[nt][0] = __float_as_uint(KL[(kk + tig) * 72 + n]);
                bl[nt][1] = __float_as_uint(KL[(kk + tig + 4) * 72 + n]);
            }
            // three passes for accumulator ILP (hh, hl, lh)
            #pragma unroll
            for (int mt = 0; mt < 4; mt++)
                #pragma unroll
                for (int nt = 0; nt < 2; nt++)
                    MMA_TF32(acc[mt * 2 + nt], ah[mt][0], ah[mt][1], ah[mt][2], ah[mt][3],
                             bh[nt][0], bh[nt][1]);
            #pragma unroll
            for (int mt = 0; mt < 4; mt++)
                #pragma unroll
                for (int nt = 0; nt < 2; nt++)
                    MMA_TF32(acc[mt * 2 + nt], ah[mt][0], ah[mt][1], ah[mt][2], ah[mt][3],
                             bl[nt][0], bl[nt][1]);
            #pragma unroll
            for (int mt = 0; mt < 4; mt++)
                #pragma unroll
                for (int nt = 0; nt < 2; nt++)
                    MMA_TF32(acc[mt * 2 + nt], al[mt][0], al[mt][1], al[mt][2], al[mt][3],
                             bh[nt][0], bh[nt][1]);
        }

        #pragma unroll
        for (int mt = 0; mt < 4; mt++) {
            int r0 = bm + wm + mt * 16 + gid;
            size_t base0 = (size_t)r0 * SEQ;
            size_t base1 = base0 + 8 * SEQ;
            #pragma unroll
            for (int nt = 0; nt < 2; nt++) {
                float* c = acc[mt * 2 + nt];
                int col = bn + sub * 64 + wn + nt * 8 + 2 * tig;
                *(float2*)(Eb + base0 + col) = make_float2(c[0], c[1]);
                *(float2*)(Eb + base1 + col) = make_float2(c[2], c[3]);
            }
        }
    }
}

// ===========================================================================
// softmax: in-place row softmax; final probs stored tf32-rounded.
// ===========================================================================
__global__ __launch_bounds__(256)
void softmax_kernel(float* __restrict__ E) {
    const int tid = threadIdx.x;
    float4* p = (float4*)(E + (size_t)blockIdx.x * SEQ);
    float4 v[4];
    float mx = -3.4e38f;
    #pragma unroll
    for (int i = 0; i < 4; i++) {
        v[i] = p[tid + i * 256];
        mx = fmaxf(mx, fmaxf(fmaxf(v[i].x, v[i].y), fmaxf(v[i].z, v[i].w)));
    }
    __shared__ float sred[8];
    #pragma unroll
    for (int o = 16; o > 0; o >>= 1) mx = fmaxf(mx, __shfl_xor_sync(0xffffffffu, mx, o));
    if ((tid & 31) == 0) sred[tid >> 5] = mx;
    __syncthreads();
    if (tid == 0) {
        float m = sred[0];
        #pragma unroll
        for (int i = 1; i < 8; i++) m = fmaxf(m, sred[i]);
        sred[0] = m;
    }
    __syncthreads();
    mx = sred[0];
    __syncthreads();

    float s = 0.f;
    #pragma unroll
    for (int i = 0; i < 4; i++) {
        v[i].x = __expf(v[i].x - mx);
        v[i].y = __expf(v[i].y - mx);
        v[i].z = __expf(v[i].z - mx);
        v[i].w = __expf(v[i].w - mx);
        s += (v[i].x + v[i].y) + (v[i].z + v[i].w);
    }
    #pragma unroll
    for (int o = 16; o > 0; o >>= 1) s += __shfl_xor_sync(0xffffffffu, s, o);
    if ((tid & 31) == 0) sred[tid >> 5] = s;
    __syncthreads();
    if (tid == 0) {
        float t = 0.f;
        #pragma unroll
        for (int i = 0; i < 8; i++) t += sred[i];
        sred[0] = t;
    }
    __syncthreads();
    float inv = 1.0f / sred[0];
    #pragma unroll
    for (int i = 0; i < 4; i++) {
        v[i].x = tf32r(v[i].x * inv);
        v[i].y = tf32r(v[i].y * inv);
        v[i].z = tf32r(v[i].z * inv);
        v[i].w = tf32r(v[i].w * inv);
        p[tid + i * 256] = v[i];
    }
}

// ===========================================================================
// av_mma: Out = gamma * (Att @ V) + X.  tf32 mma.sync, 128x128xK32 tiles,
// 3-stage cp.async pipeline (2 loads in flight), 8 warps of 64x32.
// ===========================================================================
#define A_STRIDE 36
#define B_STRIDE 136
#define A_STAGE_F (128 * A_STRIDE)
#define B_STAGE_F (32 * B_STRIDE)
#define AV_NBUF 3
#define AV_SMEM_F (AV_NBUF * (A_STAGE_F + B_STAGE_F))   // 26880 floats
#define AV_SMEM_BYTES (AV_SMEM_F * 4)                   // 107520

__device__ __forceinline__ void av_load_stage(uint32_t sb, const float* __restrict__ Ab,
                                              const float* __restrict__ Vb,
                                              int k0, int buf, int tid, int bn) {
    uint32_t abase = sb + buf * (A_STAGE_F * 4);
    #pragma unroll
    for (int j = 0; j < 4; j++) {
        int idx = tid + j * 256;
        int r   = idx >> 3;
        int c   = idx & 7;
        cp16(abase + (r * A_STRIDE + c * 4) * 4, Ab + (size_t)r * SEQ + k0 + c * 4);
    }
    uint32_t bbase = sb + (AV_NBUF * A_STAGE_F + buf * B_STAGE_F) * 4;
    #pragma unroll
    for (int j = 0; j < 4; j++) {
        int idx = tid + j * 256;
        int kr  = idx >> 5;
        int c   = idx & 31;
        cp16(bbase + (kr * B_STRIDE + c * 4) * 4, Vb + (size_t)(k0 + kr) * CH + bn + c * 4);
    }
}

__global__ __launch_bounds__(256, 2)
void av_mma_kernel(const float* __restrict__ Att, const float* __restrict__ V,
                   const float* __restrict__ X, const float* __restrict__ gamma,
                   float* __restrict__ Out) {
    extern __shared__ float smemf[];
    uint32_t sb = smem_u32(smemf);
    const int tid  = threadIdx.x;
    const int wid  = tid >> 5;
    const int lane = tid & 31;
    const int gid  = lane >> 2;
    const int tig  = lane & 3;
    const int wm   = (wid >> 2) * 64;
    const int wn   = (wid & 3) * 32;

    const int bz = blockIdx.z;
    const int bm = blockIdx.y * 128;
    const int bn = blockIdx.x * 128;
    const float* Ab = Att + ((size_t)bz * SEQ + bm) * SEQ;
    const float* Vb = V   + (size_t)bz * SEQ * CH;

    float acc[16][4];
    #pragma unroll
    for (int i = 0; i < 16; i++)
        #pragma unroll
        for (int j = 0; j < 4; j++) acc[i][j] = 0.f;

    av_load_stage(sb, Ab, Vb, 0,  0, tid, bn); CP_COMMIT();
    av_load_stage(sb, Ab, Vb, 32, 1, tid, bn); CP_COMMIT();
    av_load_stage(sb, Ab, Vb, 64, 2, tid, bn); CP_COMMIT();

    const int NS = SEQ / 32;   // 128
    for (int s = 0; s < NS; s++) {
        const int buf = s % 3;
        if (s + 2 < NS)      { CP_WAIT_2(); }
        else if (s + 1 < NS) { CP_WAIT_1(); }
        else                 { CP_WAIT_0(); }
        __syncthreads();

        const float* As = smemf + buf * A_STAGE_F;
        const float* Bs = smemf + AV_NBUF * A_STAGE_F + buf * B_STAGE_F;

        #pragma unroll
        for (int kk = 0; kk < 32; kk += 8) {
            uint32_t a[4][4], b[4][2];
            #pragma unroll
            for (int mt = 0; mt < 4; mt++) {
                int r = wm + mt * 16 + gid;
                a[mt][0] = __float_as_uint(As[r * A_STRIDE + kk + tig]);
                a[mt][1] = __float_as_uint(As[(r + 8) * A_STRIDE + kk + tig]);
                a[mt][2] = __float_as_uint(As[r * A_STRIDE + kk + tig + 4]);
                a[mt][3] = __float_as_uint(As[(r + 8) * A_STRIDE + kk + tig + 4]);
            }
            #pragma unroll
            for (int nt = 0; nt < 4; nt++) {
                int n = wn + nt * 8 + gid;
                b[nt][0] = __float_as_uint(Bs[(kk + tig) * B_STRIDE + n]);
                b[nt][1] = __float_as_uint(Bs[(kk + tig + 4) * B_STRIDE + n]);
            }
            #pragma unroll
            for (int mt = 0; mt < 4; mt++)
                #pragma unroll
                for (int nt = 0; nt < 4; nt++)
                    MMA_TF32(acc[mt * 4 + nt], a[mt][0], a[mt][1], a[mt][2], a[mt][3],
                             b[nt][0], b[nt][1]);
        }
        __syncthreads();
        if (s + 3 < NS) {
            av_load_stage(sb, Ab, Vb, (s + 3) * 32, buf, tid, bn);
            CP_COMMIT();
        }
    }

    const float g = gamma[0];
    #pragma unroll
    for (int mt = 0; mt < 4; mt++) {
        int r0 = bm + wm + mt * 16 + gid;
        size_t base0 = ((size_t)bz * SEQ + r0) * CH;
        size_t base1 = base0 + 8 * CH;
        #pragma unroll
        for (int nt = 0; nt < 4; nt++) {
            float* c = acc[mt * 4 + nt];
            int col = bn + wn + nt * 8 + 2 * tig;
            float2 x0 = *(const float2*)(X + base0 + col);
            float2 x1 = *(const float2*)(X + base1 + col);
            float2 o0, o1;
            o0.x = fmaf(g, c[0], x0.x); o0.y = fmaf(g, c[1], x0.y);
            o1.x = fmaf(g, c[2], x1.x); o1.y = fmaf(g, c[3], x1.y);
            *(float2*)(Out + base0 + col) = o0;
            *(float2*)(Out + base1 + col) = o1;
        }
    }
}

// ===========================================================================
extern "C" void kernel_launch(void* const* d_in, const int* in_sizes, int n_in,
                              void* d_out, int out_size) {
    const float* x     = (const float*)d_in[0];
    const float* Wq    = (const float*)d_in[1];
    const float* bq    = (const float*)d_in[2];
    const float* Wk    = (const float*)d_in[3];
    const float* bk    = (const float*)d_in[4];
    const float* Wv    = (const float*)d_in[5];
    const float* bv    = (const float*)d_in[6];
    const float* gamma = (const float*)d_in[7];

    float* out = (float*)d_out;                              // [B, N, C]
    float* att = out + (size_t)BATCH * SEQ * CH;             // [B, N, N]

    float *qh, *ql, *k, *kTh, *kTl, *v;
    cudaGetSymbolAddress((void**)&qh,  g_qh);
    cudaGetSymbolAddress((void**)&ql,  g_ql);
    cudaGetSymbolAddress((void**)&k,   g_k);
    cudaGetSymbolAddress((void**)&kTh, g_kTh);
    cudaGetSymbolAddress((void**)&kTl, g_kTl);
    cudaGetSymbolAddress((void**)&v,   g_v);

    static bool attr_set = false;
    if (!attr_set) {
        cudaFuncSetAttribute(av_mma_kernel, cudaFuncAttributeMaxDynamicSharedMemorySize, AV_SMEM_BYTES);
        cudaFuncSetAttribute(energy_mma_kernel, cudaFuncAttributeMaxDynamicSharedMemorySize, E_SMEM_BYTES);
        attr_set = true;
    }

    const int M = BATCH * SEQ;  // 65536

    // Projections: q pre-split hi/lo; k plain (split+transposed below); v tf32-rounded
    proj_kernel<<<dim3(DIM / 64, M / 128), 256>>>(x, Wq, bq, qh, ql, DIM, 0);
    proj_kernel<<<dim3(DIM / 64, M / 128), 256>>>(x, Wk, bk, k, nullptr, DIM, 0);
    proj_kernel<<<dim3(CH  / 64, M / 128), 256>>>(x, Wv, bv, v, nullptr, CH, 1);

    // k -> kT hi/lo (transpose + Dekker split)
    ksplit_kernel<<<dim3(DIM / 32, SEQ / 32, BATCH), dim3(32, 8)>>>(k, kTh, kTl);

    // Logits on tensor cores (pre-split operands, zero cvt in hot loop)
    energy_mma_kernel<<<dim3(SEQ / 128, SEQ / 128, BATCH), 256, E_SMEM_BYTES>>>(qh, ql, kTh, kTl, att);

    // In-place row softmax (stores tf32-rounded probs)
    softmax_kernel<<<M, 256>>>(att);

    // attn @ V on tensor cores, 3-stage pipeline, fused gamma-residual
    av_mma_kernel<<<dim3(CH / 128, SEQ / 128, BATCH), 256, AV_SMEM_BYTES>>>(att, v, x, gamma, out);
}

// round 12
// speedup vs baseline: 1.0360x; 1.0360x over previous
#include <cuda_runtime.h>
#include <cstdint>

#define BATCH 16
#define SEQ   4096
#define CH    512
#define DIM   64

// Scratch (allocation-free per harness rules)
__device__ float g_qh[BATCH * SEQ * DIM];
__device__ float g_ql[BATCH * SEQ * DIM];
__device__ float g_k [BATCH * SEQ * DIM];
__device__ float g_kTh[BATCH * DIM * SEQ];   // [b, d, n] hi
__device__ float g_kTl[BATCH * DIM * SEQ];   // [b, d, n] lo
__device__ float g_v [BATCH * SEQ * CH];

// ===========================================================================
// helpers
// ===========================================================================
__device__ __forceinline__ uint32_t smem_u32(const void* p) {
    uint32_t a;
    asm("{ .reg .u64 t; cvta.to.shared.u64 t, %1; cvt.u32.u64 %0, t; }" : "=r"(a) : "l"(p));
    return a;
}
__device__ __forceinline__ float tf32r(float x) {
    uint32_t r;
    asm("cvt.rna.tf32.f32 %0, %1;" : "=r"(r) : "f"(x));
    return __uint_as_float(r);
}
__device__ __forceinline__ void cp16(uint32_t dst, const void* src) {
    asm volatile("cp.async.cg.shared.global [%0], [%1], 16;" :: "r"(dst), "l"(src));
}
#define CP_COMMIT() asm volatile("cp.async.commit_group;" ::: "memory")
#define CP_WAIT_2() asm volatile("cp.async.wait_group 2;" ::: "memory")
#define CP_WAIT_1() asm volatile("cp.async.wait_group 1;" ::: "memory")
#define CP_WAIT_0() asm volatile("cp.async.wait_group 0;" ::: "memory")

#define MMA_TF32(c, a0, a1, a2, a3, b0, b1) \
    asm volatile( \
        "mma.sync.aligned.m16n8k8.row.col.f32.tf32.tf32.f32 " \
        "{%0,%1,%2,%3}, {%4,%5,%6,%7}, {%8,%9}, {%0,%1,%2,%3};" \
        : "+f"((c)[0]), "+f"((c)[1]), "+f"((c)[2]), "+f"((c)[3]) \
        : "r"(a0), "r"(a1), "r"(a2), "r"(a3), "r"(b0), "r"(b1))

// ===========================================================================
// proj: C[M,N] = A[M,512] @ W[512,N] + bias.
// round_out=1: store tf32-rounded.  C_lo != null: store Dekker hi/lo pair.
// ===========================================================================
__global__ __launch_bounds__(256, 2)
void proj_kernel(const float* __restrict__ A, const float* __restrict__ W,
                 const float* __restrict__ bias, float* __restrict__ C,
                 float* __restrict__ C_lo, int N, int round_out) {
    const int K = CH;
    __shared__ float As[32][132];
    __shared__ float Ws[32][64];
    const int bm = blockIdx.y * 128;
    const int bn = blockIdx.x * 64;
    const int tid = threadIdx.x;
    const int tn = tid & 15;
    const int tm = tid >> 4;
    float acc[8][4] = {};

    for (int k0 = 0; k0 < K; k0 += 32) {
        #pragma unroll
        for (int i = 0; i < 4; i++) {
            int fidx = tid + i * 256;
            int row  = fidx >> 3;
            int kc   = (fidx & 7) * 4;
            float4 t = *(const float4*)(A + (size_t)(bm + row) * K + k0 + kc);
            As[kc + 0][row] = t.x; As[kc + 1][row] = t.y;
            As[kc + 2][row] = t.z; As[kc + 3][row] = t.w;
        }
        #pragma unroll
        for (int i = 0; i < 2; i++) {
            int fidx = tid + i * 256;
            int kr   = fidx >> 4;
            int nc   = (fidx & 15) * 4;
            *(float4*)&Ws[kr][nc] = *(const float4*)(W + (size_t)(k0 + kr) * N + bn + nc);
        }
        __syncthreads();
        #pragma unroll
        for (int kk = 0; kk < 32; kk++) {
            float4 a0 = *(const float4*)&As[kk][tm * 8];
            float4 a1 = *(const float4*)&As[kk][tm * 8 + 4];
            float4 w0 = *(const float4*)&Ws[kk][tn * 4];
            float a[8] = {a0.x, a0.y, a0.z, a0.w, a1.x, a1.y, a1.z, a1.w};
            float w[4] = {w0.x, w0.y, w0.z, w0.w};
            #pragma unroll
            for (int i = 0; i < 8; i++)
                #pragma unroll
                for (int j = 0; j < 4; j++)
                    acc[i][j] = fmaf(a[i], w[j], acc[i][j]);
        }
        __syncthreads();
    }
    #pragma unroll
    for (int i = 0; i < 8; i++) {
        size_t row = bm + tm * 8 + i;
        int col = bn + tn * 4;
        float4 o;
        o.x = acc[i][0] + bias[col + 0];
        o.y = acc[i][1] + bias[col + 1];
        o.z = acc[i][2] + bias[col + 2];
        o.w = acc[i][3] + bias[col + 3];
        if (C_lo) {
            float4 h, l;
            h.x = tf32r(o.x); l.x = tf32r(o.x - h.x);
            h.y = tf32r(o.y); l.y = tf32r(o.y - h.y);
            h.z = tf32r(o.z); l.z = tf32r(o.z - h.z);
            h.w = tf32r(o.w); l.w = tf32r(o.w - h.w);
            *(float4*)(C    + row * N + col) = h;
            *(float4*)(C_lo + row * N + col) = l;
        } else {
            if (round_out) {
                o.x = tf32r(o.x); o.y = tf32r(o.y);
                o.z = tf32r(o.z); o.w = tf32r(o.w);
            }
            *(float4*)(C + row * N + col) = o;
        }
    }
}

// ===========================================================================
// ksplit: k[b,n,d] -> kT_hi/kT_lo [b,d,n]  (transpose + Dekker split)
// ===========================================================================
__global__ __launch_bounds__(256)
void ksplit_kernel(const float* __restrict__ K, float* __restrict__ KTh,
                   float* __restrict__ KTl) {
    __shared__ float t[32][33];
    const int b  = blockIdx.z;
    const int d0 = blockIdx.x * 32;
    const int n0 = blockIdx.y * 32;
    const float* Kb = K + (size_t)b * SEQ * DIM;
    const size_t tb = (size_t)b * DIM * SEQ;
    const int tx = threadIdx.x, ty = threadIdx.y;
    #pragma unroll
    for (int j = 0; j < 4; j++)
        t[ty + j * 8][tx] = Kb[(size_t)(n0 + ty + j * 8) * DIM + d0 + tx];
    __syncthreads();
    #pragma unroll
    for (int j = 0; j < 4; j++) {
        float v = t[tx][ty + j * 8];
        float h = tf32r(v);
        size_t off = tb + (size_t)(d0 + ty + j * 8) * SEQ + n0 + tx;
        KTh[off] = h;
        KTl[off] = tf32r(v - h);
    }
}

// ===========================================================================
// energy_mma: E[b,m,n] = QK^T on tensor cores, PRE-SPLIT hi/lo operands.
// Round-10 verified tiling: 128m x 64n, K=64 whole reduction, 8 warps of
// 64m x 16n, 2 CTAs/SM.  Zero cvt/sub in hot loop (the round-10 alu=42.8%).
// Smem: Ah,Al [128][68] + Kh,Kl [64][72] = 106496 B.
// ===========================================================================
#define EAH_OFF 0
#define EAL_OFF 8704                       // 128*68
#define EKH_OFF 17408
#define EKL_OFF 22016                      // +64*72
#define E_SMEM_F 26624
#define E_SMEM_BYTES (E_SMEM_F * 4)        // 106496

__global__ __launch_bounds__(256, 2)
void energy_mma_kernel(const float* __restrict__ Qh, const float* __restrict__ Ql,
                       const float* __restrict__ KTh, const float* __restrict__ KTl,
                       float* __restrict__ E) {
    extern __shared__ float smemf[];
    uint32_t sb = smem_u32(smemf);

    const int tid  = threadIdx.x;
    const int wid  = tid >> 5;
    const int lane = tid & 31;
    const int gid  = lane >> 2;      // 0..7
    const int tig  = lane & 3;       // 0..3
    const int wm   = (wid >> 2) * 64;    // 0 or 64
    const int wn   = (wid & 3) * 16;     // 0,16,32,48

    const int bz = blockIdx.z;
    const int bm = blockIdx.y * 128;
    const int bn = blockIdx.x * 64;
    const float* Qhb = Qh + ((size_t)bz * SEQ + bm) * DIM;
    const float* Qlb = Ql + ((size_t)bz * SEQ + bm) * DIM;
    const float* KThb = KTh + (size_t)bz * DIM * SEQ + bn;
    const float* KTlb = KTl + (size_t)bz * DIM * SEQ + bn;
    float* Eb = E + (size_t)bz * SEQ * SEQ;

    // A hi/lo: 128 rows x 64 (16 chunks of 16B), stride 68
    #pragma unroll
    for (int j = 0; j < 8; j++) {
        int idx = tid + j * 256;     // 0..2047
        int r   = idx >> 4;          // 0..127
        int c   = idx & 15;
        cp16(sb + (uint32_t)(EAH_OFF + r * 68 + c * 4) * 4, Qhb + (size_t)r * DIM + c * 4);
        cp16(sb + (uint32_t)(EAL_OFF + r * 68 + c * 4) * 4, Qlb + (size_t)r * DIM + c * 4);
    }
    // K hi/lo: 64 d-rows x 64 n (16 chunks), stride 72  (already [d][n] in gmem)
    #pragma unroll
    for (int j = 0; j < 4; j++) {
        int idx = tid + j * 256;     // 0..1023
        int d   = idx >> 4;          // 0..63
        int c   = idx & 15;
        cp16(sb + (uint32_t)(EKH_OFF + d * 72 + c * 4) * 4, KThb + (size_t)d * SEQ + c * 4);
        cp16(sb + (uint32_t)(EKL_OFF + d * 72 + c * 4) * 4, KTlb + (size_t)d * SEQ + c * 4);
    }
    CP_COMMIT();
    CP_WAIT_0();
    __syncthreads();

    const float* AH = smemf + EAH_OFF;
    const float* AL = smemf + EAL_OFF;
    const float* KH = smemf + EKH_OFF;
    const float* KL = smemf + EKL_OFF;

    float acc[8][4];
    #pragma unroll
    for (int i = 0; i < 8; i++)
        #pragma unroll
        for (int j = 0; j < 4; j++) acc[i][j] = 0.f;

    #pragma unroll
    for (int kk = 0; kk < 64; kk += 8) {
        uint32_t ah[4][4], al[4][4], bh[2][2], bl[2][2];
        #pragma unroll
        for (int mt = 0; mt < 4; mt++) {
            int r = wm + mt * 16 + gid;
            ah[mt][0] = __float_as_uint(AH[r * 68 + kk + tig]);
            ah[mt][1] = __float_as_uint(AH[(r + 8) * 68 + kk + tig]);
            ah[mt][2] = __float_as_uint(AH[r * 68 + kk + tig + 4]);
            ah[mt][3] = __float_as_uint(AH[(r + 8) * 68 + kk + tig + 4]);
            al[mt][0] = __float_as_uint(AL[r * 68 + kk + tig]);
            al[mt][1] = __float_as_uint(AL[(r + 8) * 68 + kk + tig]);
            al[mt][2] = __float_as_uint(AL[r * 68 + kk + tig + 4]);
            al[mt][3] = __float_as_uint(AL[(r + 8) * 68 + kk + tig + 4]);
        }
        #pragma unroll
        for (int nt = 0; nt < 2; nt++) {
            int n = wn + nt * 8 + gid;
            bh[nt][0] = __float_as_uint(KH[(kk + tig) * 72 + n]);
            bh[nt][1] = __float_as_uint(KH[(kk + tig + 4) * 72 + n]);
            bl[nt][0] = __float_as_uint(KL[(kk + tig) * 72 + n]);
            bl[nt][1] = __float_as_uint(KL[(kk + tig + 4) * 72 + n]);
        }
        // three passes (hh, hl, lh) — 8 independent accumulators per pass
        #pragma unroll
        for (int mt = 0; mt < 4; mt++)
            #pragma unroll
            for (int nt = 0; nt < 2; nt++)
                MMA_TF32(acc[mt * 2 + nt], ah[mt][0], ah[mt][1], ah[mt][2], ah[mt][3],
                         bh[nt][0], bh[nt][1]);
        #pragma unroll
        for (int mt = 0; mt < 4; mt++)
            #pragma unroll
            for (int nt = 0; nt < 2; nt++)
                MMA_TF32(acc[mt * 2 + nt], ah[mt][0], ah[mt][1], ah[mt][2], ah[mt][3],
                         bl[nt][0], bl[nt][1]);
        #pragma unroll
        for (int mt = 0; mt < 4; mt++)
            #pragma unroll
            for (int nt = 0; nt < 2; nt++)
                MMA_TF32(acc[mt * 2 + nt], al[mt][0], al[mt][1], al[mt][2], al[mt][3],
                         bh[nt][0], bh[nt][1]);
    }

    // write logits
    #pragma unroll
    for (int mt = 0; mt < 4; mt++) {
        int r0 = bm + wm + mt * 16 + gid;
        size_t base0 = (size_t)r0 * SEQ;
        size_t base1 = base0 + 8 * SEQ;
        #pragma unroll
        for (int nt = 0; nt < 2; nt++) {
            float* c = acc[mt * 2 + nt];
            int col = bn + wn + nt * 8 + 2 * tig;
            *(float2*)(Eb + base0 + col) = make_float2(c[0], c[1]);
            *(float2*)(Eb + base1 + col) = make_float2(c[2], c[3]);
        }
    }
}

// ===========================================================================
// softmax: in-place row softmax; final probs stored tf32-rounded.
// ===========================================================================
__global__ __launch_bounds__(256)
void softmax_kernel(float* __restrict__ E) {
    const int tid = threadIdx.x;
    float4* p = (float4*)(E + (size_t)blockIdx.x * SEQ);
    float4 v[4];
    float mx = -3.4e38f;
    #pragma unroll
    for (int i = 0; i < 4; i++) {
        v[i] = p[tid + i * 256];
        mx = fmaxf(mx, fmaxf(fmaxf(v[i].x, v[i].y), fmaxf(v[i].z, v[i].w)));
    }
    __shared__ float sred[8];
    #pragma unroll
    for (int o = 16; o > 0; o >>= 1) mx = fmaxf(mx, __shfl_xor_sync(0xffffffffu, mx, o));
    if ((tid & 31) == 0) sred[tid >> 5] = mx;
    __syncthreads();
    if (tid == 0) {
        float m = sred[0];
        #pragma unroll
        for (int i = 1; i < 8; i++) m = fmaxf(m, sred[i]);
        sred[0] = m;
    }
    __syncthreads();
    mx = sred[0];
    __syncthreads();

    float s = 0.f;
    #pragma unroll
    for (int i = 0; i < 4; i++) {
        v[i].x = __expf(v[i].x - mx);
        v[i].y = __expf(v[i].y - mx);
        v[i].z = __expf(v[i].z - mx);
        v[i].w = __expf(v[i].w - mx);
        s += (v[i].x + v[i].y) + (v[i].z + v[i].w);
    }
    #pragma unroll
    for (int o = 16; o > 0; o >>= 1) s += __shfl_xor_sync(0xffffffffu, s, o);
    if ((tid & 31) == 0) sred[tid >> 5] = s;
    __syncthreads();
    if (tid == 0) {
        float t = 0.f;
        #pragma unroll
        for (int i = 0; i < 8; i++) t += sred[i];
        sred[0] = t;
    }
    __syncthreads();
    float inv = 1.0f / sred[0];
    #pragma unroll
    for (int i = 0; i < 4; i++) {
        v[i].x = tf32r(v[i].x * inv);
        v[i].y = tf32r(v[i].y * inv);
        v[i].z = tf32r(v[i].z * inv);
        v[i].w = tf32r(v[i].w * inv);
        p[tid + i * 256] = v[i];
    }
}

// ===========================================================================
// av_mma: Out = gamma * (Att @ V) + X.  tf32 mma.sync, 128x128xK32 tiles,
// 3-stage cp.async pipeline, 8 warps of 64x32, 2 CTAs/SM.
// ===========================================================================
#define A_STRIDE 36
#define B_STRIDE 136
#define A_STAGE_F (128 * A_STRIDE)
#define B_STAGE_F (32 * B_STRIDE)
#define AV_NBUF 3
#define AV_SMEM_F (AV_NBUF * (A_STAGE_F + B_STAGE_F))
#define AV_SMEM_BYTES (AV_SMEM_F * 4)                   // 107520

__device__ __forceinline__ void av_load_stage(uint32_t sb, const float* __restrict__ Ab,
                                              const float* __restrict__ Vb,
                                              int k0, int buf, int tid, int bn) {
    uint32_t abase = sb + buf * (A_STAGE_F * 4);
    #pragma unroll
    for (int j = 0; j < 4; j++) {
        int idx = tid + j * 256;
        int r   = idx >> 3;
        int c   = idx & 7;
        cp16(abase + (r * A_STRIDE + c * 4) * 4, Ab + (size_t)r * SEQ + k0 + c * 4);
    }
    uint32_t bbase = sb + (AV_NBUF * A_STAGE_F + buf * B_STAGE_F) * 4;
    #pragma unroll
    for (int j = 0; j < 4; j++) {
        int idx = tid + j * 256;
        int kr  = idx >> 5;
        int c   = idx & 31;
        cp16(bbase + (kr * B_STRIDE + c * 4) * 4, Vb + (size_t)(k0 + kr) * CH + bn + c * 4);
    }
}

__global__ __launch_bounds__(256, 2)
void av_mma_kernel(const float* __restrict__ Att, const float* __restrict__ V,
                   const float* __restrict__ X, const float* __restrict__ gamma,
                   float* __restrict__ Out) {
    extern __shared__ float smemf[];
    uint32_t sb = smem_u32(smemf);
    const int tid  = threadIdx.x;
    const int wid  = tid >> 5;
    const int lane = tid & 31;
    const int gid  = lane >> 2;
    const int tig  = lane & 3;
    const int wm   = (wid >> 2) * 64;
    const int wn   = (wid & 3) * 32;

    const int bz = blockIdx.z;
    const int bm = blockIdx.y * 128;
    const int bn = blockIdx.x * 128;
    const float* Ab = Att + ((size_t)bz * SEQ + bm) * SEQ;
    const float* Vb = V   + (size_t)bz * SEQ * CH;

    float acc[16][4];
    #pragma unroll
    for (int i = 0; i < 16; i++)
        #pragma unroll
        for (int j = 0; j < 4; j++) acc[i][j] = 0.f;

    av_load_stage(sb, Ab, Vb, 0,  0, tid, bn); CP_COMMIT();
    av_load_stage(sb, Ab, Vb, 32, 1, tid, bn); CP_COMMIT();
    av_load_stage(sb, Ab, Vb, 64, 2, tid, bn); CP_COMMIT();

    const int NS = SEQ / 32;   // 128
    for (int s = 0; s < NS; s++) {
        const int buf = s % 3;
        if (s + 2 < NS)      { CP_WAIT_2(); }
        else if (s + 1 < NS) { CP_WAIT_1(); }
        else                 { CP_WAIT_0(); }
        __syncthreads();

        const float* As = smemf + buf * A_STAGE_F;
        const float* Bs = smemf + AV_NBUF * A_STAGE_F + buf * B_STAGE_F;

        #pragma unroll
        for (int kk = 0; kk < 32; kk += 8) {
            uint32_t a[4][4], b[4][2];
            #pragma unroll
            for (int mt = 0; mt < 4; mt++) {
                int r = wm + mt * 16 + gid;
                a[mt][0] = __float_as_uint(As[r * A_STRIDE + kk + tig]);
                a[mt][1] = __float_as_uint(As[(r + 8) * A_STRIDE + kk + tig]);
                a[mt][2] = __float_as_uint(As[r * A_STRIDE + kk + tig + 4]);
                a[mt][3] = __float_as_uint(As[(r + 8) * A_STRIDE + kk + tig + 4]);
            }
            #pragma unroll
            for (int nt = 0; nt < 4; nt++) {
                int n = wn + nt * 8 + gid;
                b[nt][0] = __float_as_uint(Bs[(kk + tig) * B_STRIDE + n]);
                b[nt][1] = __float_as_uint(Bs[(kk + tig + 4) * B_STRIDE + n]);
            }
            #pragma unroll
            for (int mt = 0; mt < 4; mt++)
                #pragma unroll
                for (int nt = 0; nt < 4; nt++)
                    MMA_TF32(acc[mt * 4 + nt], a[mt][0], a[mt][1], a[mt][2], a[mt][3],
                             b[nt][0], b[nt][1]);
        }
        __syncthreads();
        if (s + 3 < NS) {
            av_load_stage(sb, Ab, Vb, (s + 3) * 32, buf, tid, bn);
            CP_COMMIT();
        }
    }

    const float g = gamma[0];
    #pragma unroll
    for (int mt = 0; mt < 4; mt++) {
        int r0 = bm + wm + mt * 16 + gid;
        size_t base0 = ((size_t)bz * SEQ + r0) * CH;
        size_t base1 = base0 + 8 * CH;
        #pragma unroll
        for (int nt = 0; nt < 4; nt++) {
            float* c = acc[mt * 4 + nt];
            int col = bn + wn + nt * 8 + 2 * tig;
            float2 x0 = *(const float2*)(X + base0 + col);
            float2 x1 = *(const float2*)(X + base1 + col);
            float2 o0, o1;
            o0.x = fmaf(g, c[0], x0.x); o0.y = fmaf(g, c[1], x0.y);
            o1.x = fmaf(g, c[2], x1.x); o1.y = fmaf(g, c[3], x1.y);
            *(float2*)(Out + base0 + col) = o0;
            *(float2*)(Out + base1 + col) = o1;
        }
    }
}

// ===========================================================================
extern "C" void kernel_launch(void* const* d_in, const int* in_sizes, int n_in,
                              void* d_out, int out_size) {
    const float* x     = (const float*)d_in[0];
    const float* Wq    = (const float*)d_in[1];
    const float* bq    = (const float*)d_in[2];
    const float* Wk    = (const float*)d_in[3];
    const float* bk    = (const float*)d_in[4];
    const float* Wv    = (const float*)d_in[5];
    const float* bv    = (const float*)d_in[6];
    const float* gamma = (const float*)d_in[7];

    float* out = (float*)d_out;                              // [B, N, C]
    float* att = out + (size_t)BATCH * SEQ * CH;             // [B, N, N]

    float *qh, *ql, *k, *kTh, *kTl, *v;
    cudaGetSymbolAddress((void**)&qh,  g_qh);
    cudaGetSymbolAddress((void**)&ql,  g_ql);
    cudaGetSymbolAddress((void**)&k,   g_k);
    cudaGetSymbolAddress((void**)&kTh, g_kTh);
    cudaGetSymbolAddress((void**)&kTl, g_kTl);
    cudaGetSymbolAddress((void**)&v,   g_v);

    static bool attr_set = false;
    if (!attr_set) {
        cudaFuncSetAttribute(av_mma_kernel, cudaFuncAttributeMaxDynamicSharedMemorySize, AV_SMEM_BYTES);
        cudaFuncSetAttribute(energy_mma_kernel, cudaFuncAttributeMaxDynamicSharedMemorySize, E_SMEM_BYTES);
        attr_set = true;
    }

    const int M = BATCH * SEQ;  // 65536

    // Projections: q pre-split hi/lo; k plain (split+transposed below); v tf32-rounded
    proj_kernel<<<dim3(DIM / 64, M / 128), 256>>>(x, Wq, bq, qh, ql, DIM, 0);
    proj_kernel<<<dim3(DIM / 64, M / 128), 256>>>(x, Wk, bk, k, nullptr, DIM, 0);
    proj_kernel<<<dim3(CH  / 64, M / 128), 256>>>(x, Wv, bv, v, nullptr, CH, 1);

    // k -> kT hi/lo (transpose + Dekker split)
    ksplit_kernel<<<dim3(DIM / 32, SEQ / 32, BATCH), dim3(32, 8)>>>(k, kTh, kTl);

    // Logits on tensor cores: round-10 tiling (2 CTAs/SM), pre-split operands
    energy_mma_kernel<<<dim3(SEQ / 64, SEQ / 128, BATCH), 256, E_SMEM_BYTES>>>(qh, ql, kTh, kTl, att);

    // In-place row softmax (stores tf32-rounded probs)
    softmax_kernel<<<M, 256>>>(att);

    // attn @ V on tensor cores, 3-stage pipeline, fused gamma-residual
    av_mma_kernel<<<dim3(CH / 128, SEQ / 128, BATCH), 256, AV_SMEM_BYTES>>>(att, v, x, gamma, out);
}

// round 13
// speedup vs baseline: 1.2611x; 1.2172x over previous
#include <cuda_runtime.h>
#include <cuda_fp16.h>
#include <cstdint>

#define BATCH 16
#define SEQ   4096
#define CH    512
#define DIM   64

// Scratch (allocation-free per harness rules)
__device__ float g_qh[BATCH * SEQ * DIM];
__device__ float g_ql[BATCH * SEQ * DIM];
__device__ float g_k [BATCH * SEQ * DIM];
__device__ float g_kTh[BATCH * DIM * SEQ];   // [b, d, n] hi
__device__ float g_kTl[BATCH * DIM * SEQ];   // [b, d, n] lo
__device__ __half2 g_v2[BATCH * (SEQ / 2) * CH];          // [b][k/2][n] pair-interleaved fp16
__device__ __half  g_p16[(size_t)BATCH * SEQ * SEQ];      // fp16 probs copy

// ===========================================================================
// helpers
// ===========================================================================
__device__ __forceinline__ uint32_t smem_u32(const void* p) {
    uint32_t a;
    asm("{ .reg .u64 t; cvta.to.shared.u64 t, %1; cvt.u32.u64 %0, t; }" : "=r"(a) : "l"(p));
    return a;
}
__device__ __forceinline__ float tf32r(float x) {
    uint32_t r;
    asm("cvt.rna.tf32.f32 %0, %1;" : "=r"(r) : "f"(x));
    return __uint_as_float(r);
}
__device__ __forceinline__ void cp16(uint32_t dst, const void* src) {
    asm volatile("cp.async.cg.shared.global [%0], [%1], 16;" :: "r"(dst), "l"(src));
}
#define CP_COMMIT() asm volatile("cp.async.commit_group;" ::: "memory")
#define CP_WAIT_2() asm volatile("cp.async.wait_group 2;" ::: "memory")
#define CP_WAIT_1() asm volatile("cp.async.wait_group 1;" ::: "memory")
#define CP_WAIT_0() asm volatile("cp.async.wait_group 0;" ::: "memory")

#define MMA_TF32(c, a0, a1, a2, a3, b0, b1) \
    asm volatile( \
        "mma.sync.aligned.m16n8k8.row.col.f32.tf32.tf32.f32 " \
        "{%0,%1,%2,%3}, {%4,%5,%6,%7}, {%8,%9}, {%0,%1,%2,%3};" \
        : "+f"((c)[0]), "+f"((c)[1]), "+f"((c)[2]), "+f"((c)[3]) \
        : "r"(a0), "r"(a1), "r"(a2), "r"(a3), "r"(b0), "r"(b1))

#define MMA_F16(c, a0, a1, a2, a3, b0, b1) \
    asm volatile( \
        "mma.sync.aligned.m16n8k16.row.col.f32.f16.f16.f32 " \
        "{%0,%1,%2,%3}, {%4,%5,%6,%7}, {%8,%9}, {%0,%1,%2,%3};" \
        : "+f"((c)[0]), "+f"((c)[1]), "+f"((c)[2]), "+f"((c)[3]) \
        : "r"(a0), "r"(a1), "r"(a2), "r"(a3), "r"(b0), "r"(b1))

// ===========================================================================
// proj: C[M,N] = A[M,512] @ W[512,N] + bias.
// C_lo != null: store Dekker hi/lo fp32 pair.  C16 != null: store fp16
// pair-interleaved [m/2][n] half2 (for the AV B operand).
// ===========================================================================
__global__ __launch_bounds__(256, 2)
void proj_kernel(const float* __restrict__ A, const float* __restrict__ W,
                 const float* __restrict__ bias, float* __restrict__ C,
                 float* __restrict__ C_lo, __half2* __restrict__ C16, int N) {
    const int K = CH;
    __shared__ float As[32][132];
    __shared__ float Ws[32][64];
    const int bm = blockIdx.y * 128;
    const int bn = blockIdx.x * 64;
    const int tid = threadIdx.x;
    const int tn = tid & 15;
    const int tm = tid >> 4;
    float acc[8][4] = {};

    for (int k0 = 0; k0 < K; k0 += 32) {
        #pragma unroll
        for (int i = 0; i < 4; i++) {
            int fidx = tid + i * 256;
            int row  = fidx >> 3;
            int kc   = (fidx & 7) * 4;
            float4 t = *(const float4*)(A + (size_t)(bm + row) * K + k0 + kc);
            As[kc + 0][row] = t.x; As[kc + 1][row] = t.y;
            As[kc + 2][row] = t.z; As[kc + 3][row] = t.w;
        }
        #pragma unroll
        for (int i = 0; i < 2; i++) {
            int fidx = tid + i * 256;
            int kr   = fidx >> 4;
            int nc   = (fidx & 15) * 4;
            *(float4*)&Ws[kr][nc] = *(const float4*)(W + (size_t)(k0 + kr) * N + bn + nc);
        }
        __syncthreads();
        #pragma unroll
        for (int kk = 0; kk < 32; kk++) {
            float4 a0 = *(const float4*)&As[kk][tm * 8];
            float4 a1 = *(const float4*)&As[kk][tm * 8 + 4];
            float4 w0 = *(const float4*)&Ws[kk][tn * 4];
            float a[8] = {a0.x, a0.y, a0.z, a0.w, a1.x, a1.y, a1.z, a1.w};
            float w[4] = {w0.x, w0.y, w0.z, w0.w};
            #pragma unroll
            for (int i = 0; i < 8; i++)
                #pragma unroll
                for (int j = 0; j < 4; j++)
                    acc[i][j] = fmaf(a[i], w[j], acc[i][j]);
        }
        __syncthreads();
    }
    if (C16) {
        // fp16 pair-interleaved: half2 at [row/2][col] = (v[row], v[row+1])
        #pragma unroll
        for (int i = 0; i < 8; i += 2) {
            size_t row2 = (size_t)(bm + tm * 8 + i) >> 1;
            #pragma unroll
            for (int j = 0; j < 4; j++) {
                int col = bn + tn * 4 + j;
                float lo = acc[i][j]     + bias[col];
                float hi = acc[i + 1][j] + bias[col];
                C16[row2 * N + col] = __floats2half2_rn(lo, hi);
            }
        }
        return;
    }
    #pragma unroll
    for (int i = 0; i < 8; i++) {
        size_t row = bm + tm * 8 + i;
        int col = bn + tn * 4;
        float4 o;
        o.x = acc[i][0] + bias[col + 0];
        o.y = acc[i][1] + bias[col + 1];
        o.z = acc[i][2] + bias[col + 2];
        o.w = acc[i][3] + bias[col + 3];
        if (C_lo) {
            float4 h, l;
            h.x = tf32r(o.x); l.x = tf32r(o.x - h.x);
            h.y = tf32r(o.y); l.y = tf32r(o.y - h.y);
            h.z = tf32r(o.z); l.z = tf32r(o.z - h.z);
            h.w = tf32r(o.w); l.w = tf32r(o.w - h.w);
            *(float4*)(C    + row * N + col) = h;
            *(float4*)(C_lo + row * N + col) = l;
        } else {
            *(float4*)(C + row * N + col) = o;
        }
    }
}

// ===========================================================================
// ksplit: k[b,n,d] -> kT_hi/kT_lo [b,d,n]  (transpose + Dekker split)
// ===========================================================================
__global__ __launch_bounds__(256)
void ksplit_kernel(const float* __restrict__ K, float* __restrict__ KTh,
                   float* __restrict__ KTl) {
    __shared__ float t[32][33];
    const int b  = blockIdx.z;
    const int d0 = blockIdx.x * 32;
    const int n0 = blockIdx.y * 32;
    const float* Kb = K + (size_t)b * SEQ * DIM;
    const size_t tb = (size_t)b * DIM * SEQ;
    const int tx = threadIdx.x, ty = threadIdx.y;
    #pragma unroll
    for (int j = 0; j < 4; j++)
        t[ty + j * 8][tx] = Kb[(size_t)(n0 + ty + j * 8) * DIM + d0 + tx];
    __syncthreads();
    #pragma unroll
    for (int j = 0; j < 4; j++) {
        float v = t[tx][ty + j * 8];
        float h = tf32r(v);
        size_t off = tb + (size_t)(d0 + ty + j * 8) * SEQ + n0 + tx;
        KTh[off] = h;
        KTl[off] = tf32r(v - h);
    }
}

// ===========================================================================
// energy_mma: E[b,m,n] = QK^T on tensor cores, pre-split hi/lo operands.
// 128m x 64n, K=64 whole reduction, 8 warps of 64m x 16n, 2 CTAs/SM.
// ===========================================================================
#define EAH_OFF 0
#define EAL_OFF 8704                       // 128*68
#define EKH_OFF 17408
#define EKL_OFF 22016                      // +64*72
#define E_SMEM_F 26624
#define E_SMEM_BYTES (E_SMEM_F * 4)        // 106496

__global__ __launch_bounds__(256, 2)
void energy_mma_kernel(const float* __restrict__ Qh, const float* __restrict__ Ql,
                       const float* __restrict__ KTh, const float* __restrict__ KTl,
                       float* __restrict__ E) {
    extern __shared__ float smemf[];
    uint32_t sb = smem_u32(smemf);

    const int tid  = threadIdx.x;
    const int wid  = tid >> 5;
    const int lane = tid & 31;
    const int gid  = lane >> 2;      // 0..7
    const int tig  = lane & 3;       // 0..3
    const int wm   = (wid >> 2) * 64;    // 0 or 64
    const int wn   = (wid & 3) * 16;     // 0,16,32,48

    const int bz = blockIdx.z;
    const int bm = blockIdx.y * 128;
    const int bn = blockIdx.x * 64;
    const float* Qhb = Qh + ((size_t)bz * SEQ + bm) * DIM;
    const float* Qlb = Ql + ((size_t)bz * SEQ + bm) * DIM;
    const float* KThb = KTh + (size_t)bz * DIM * SEQ + bn;
    const float* KTlb = KTl + (size_t)bz * DIM * SEQ + bn;
    float* Eb = E + (size_t)bz * SEQ * SEQ;

    #pragma unroll
    for (int j = 0; j < 8; j++) {
        int idx = tid + j * 256;
        int r   = idx >> 4;
        int c   = idx & 15;
        cp16(sb + (uint32_t)(EAH_OFF + r * 68 + c * 4) * 4, Qhb + (size_t)r * DIM + c * 4);
        cp16(sb + (uint32_t)(EAL_OFF + r * 68 + c * 4) * 4, Qlb + (size_t)r * DIM + c * 4);
    }
    #pragma unroll
    for (int j = 0; j < 4; j++) {
        int idx = tid + j * 256;
        int d   = idx >> 4;
        int c   = idx & 15;
        cp16(sb + (uint32_t)(EKH_OFF + d * 72 + c * 4) * 4, KThb + (size_t)d * SEQ + c * 4);
        cp16(sb + (uint32_t)(EKL_OFF + d * 72 + c * 4) * 4, KTlb + (size_t)d * SEQ + c * 4);
    }
    CP_COMMIT();
    CP_WAIT_0();
    __syncthreads();

    const float* AH = smemf + EAH_OFF;
    const float* AL = smemf + EAL_OFF;
    const float* KH = smemf + EKH_OFF;
    const float* KL = smemf + EKL_OFF;

    float acc[8][4];
    #pragma unroll
    for (int i = 0; i < 8; i++)
        #pragma unroll
        for (int j = 0; j < 4; j++) acc[i][j] = 0.f;

    #pragma unroll
    for (int kk = 0; kk < 64; kk += 8) {
        uint32_t ah[4][4], al[4][4], bh[2][2], bl[2][2];
        #pragma unroll
        for (int mt = 0; mt < 4; mt++) {
            int r = wm + mt * 16 + gid;
            ah[mt][0] = __float_as_uint(AH[r * 68 + kk + tig]);
            ah[mt][1] = __float_as_uint(AH[(r + 8) * 68 + kk + tig]);
            ah[mt][2] = __float_as_uint(AH[r * 68 + kk + tig + 4]);
            ah[mt][3] = __float_as_uint(AH[(r + 8) * 68 + kk + tig + 4]);
            al[mt][0] = __float_as_uint(AL[r * 68 + kk + tig]);
            al[mt][1] = __float_as_uint(AL[(r + 8) * 68 + kk + tig]);
            al[mt][2] = __float_as_uint(AL[r * 68 + kk + tig + 4]);
            al[mt][3] = __float_as_uint(AL[(r + 8) * 68 + kk + tig + 4]);
        }
        #pragma unroll
        for (int nt = 0; nt < 2; nt++) {
            int n = wn + nt * 8 + gid;
            bh[nt][0] = __float_as_uint(KH[(kk + tig) * 72 + n]);
            bh[nt][1] = __float_as_uint(KH[(kk + tig + 4) * 72 + n]);
            bl[nt][0] = __float_as_uint(KL[(kk + tig) * 72 + n]);
            bl[nt][1] = __float_as_uint(KL[(kk + tig + 4) * 72 + n]);
        }
        #pragma unroll
        for (int mt = 0; mt < 4; mt++)
            #pragma unroll
            for (int nt = 0; nt < 2; nt++)
                MMA_TF32(acc[mt * 2 + nt], ah[mt][0], ah[mt][1], ah[mt][2], ah[mt][3],
                         bh[nt][0], bh[nt][1]);
        #pragma unroll
        for (int mt = 0; mt < 4; mt++)
            #pragma unroll
            for (int nt = 0; nt < 2; nt++)
                MMA_TF32(acc[mt * 2 + nt], ah[mt][0], ah[mt][1], ah[mt][2], ah[mt][3],
                         bl[nt][0], bl[nt][1]);
        #pragma unroll
        for (int mt = 0; mt < 4; mt++)
            #pragma unroll
            for (int nt = 0; nt < 2; nt++)
                MMA_TF32(acc[mt * 2 + nt], al[mt][0], al[mt][1], al[mt][2], al[mt][3],
                         bh[nt][0], bh[nt][1]);
    }

    #pragma unroll
    for (int mt = 0; mt < 4; mt++) {
        int r0 = bm + wm + mt * 16 + gid;
        size_t base0 = (size_t)r0 * SEQ;
        size_t base1 = base0 + 8 * SEQ;
        #pragma unroll
        for (int nt = 0; nt < 2; nt++) {
            float* c = acc[mt * 2 + nt];
            int col = bn + wn + nt * 8 + 2 * tig;
            *(float2*)(Eb + base0 + col) = make_float2(c[0], c[1]);
            *(float2*)(Eb + base1 + col) = make_float2(c[2], c[3]);
        }
    }
}

// ===========================================================================
// softmax: in-place row softmax. fp32 probs to E (checked output, full
// precision) + fp16 copy to P16 (AV operand).
// ===========================================================================
__global__ __launch_bounds__(256)
void softmax_kernel(float* __restrict__ E, __half* __restrict__ P16) {
    const int tid = threadIdx.x;
    const size_t base = (size_t)blockIdx.x * SEQ;
    float4* p = (float4*)(E + base);
    float4 v[4];
    float mx = -3.4e38f;
    #pragma unroll
    for (int i = 0; i < 4; i++) {
        v[i] = p[tid + i * 256];
        mx = fmaxf(mx, fmaxf(fmaxf(v[i].x, v[i].y), fmaxf(v[i].z, v[i].w)));
    }
    __shared__ float sred[8];
    #pragma unroll
    for (int o = 16; o > 0; o >>= 1) mx = fmaxf(mx, __shfl_xor_sync(0xffffffffu, mx, o));
    if ((tid & 31) == 0) sred[tid >> 5] = mx;
    __syncthreads();
    if (tid == 0) {
        float m = sred[0];
        #pragma unroll
        for (int i = 1; i < 8; i++) m = fmaxf(m, sred[i]);
        sred[0] = m;
    }
    __syncthreads();
    mx = sred[0];
    __syncthreads();

    float s = 0.f;
    #pragma unroll
    for (int i = 0; i < 4; i++) {
        v[i].x = __expf(v[i].x - mx);
        v[i].y = __expf(v[i].y - mx);
        v[i].z = __expf(v[i].z - mx);
        v[i].w = __expf(v[i].w - mx);
        s += (v[i].x + v[i].y) + (v[i].z + v[i].w);
    }
    #pragma unroll
    for (int o = 16; o > 0; o >>= 1) s += __shfl_xor_sync(0xffffffffu, s, o);
    if ((tid & 31) == 0) sred[tid >> 5] = s;
    __syncthreads();
    if (tid == 0) {
        float t = 0.f;
        #pragma unroll
        for (int i = 0; i < 8; i++) t += sred[i];
        sred[0] = t;
    }
    __syncthreads();
    float inv = 1.0f / sred[0];
    #pragma unroll
    for (int i = 0; i < 4; i++) {
        v[i].x *= inv; v[i].y *= inv; v[i].z *= inv; v[i].w *= inv;
        p[tid + i * 256] = v[i];
        __half2 h01 = __floats2half2_rn(v[i].x, v[i].y);
        __half2 h23 = __floats2half2_rn(v[i].z, v[i].w);
        uint2 pk;
        pk.x = *(uint32_t*)&h01;
        pk.y = *(uint32_t*)&h23;
        *(uint2*)(P16 + base + (size_t)(tid + i * 256) * 4) = pk;
    }
}

// ===========================================================================
// av_mma: Out = gamma * (Att @ V) + X on fp16 m16n8k16 tensor cores.
// Block 128x128xK32, 8 warps of 64x32, 3-stage cp.async pipeline.
// A: fp16 probs row-major [128][32], word-stride 20 (16 data + 4 pad).
// B: V pair-interleaved half2 [16 k2][128 n], word-stride 136.
// ===========================================================================
#define AVA_W 20
#define AVB_W 136
#define AVA_ST (128 * AVA_W)     // 2560 words
#define AVB_ST (16 * AVB_W)      // 2176 words
#define AV_NBUF 3
#define AV_SMEM_W (AV_NBUF * (AVA_ST + AVB_ST))   // 14208 words
#define AV_SMEM_BYTES (AV_SMEM_W * 4)             // 56832

__device__ __forceinline__ void av_load_stage(uint32_t sb, const __half* __restrict__ Ab,
                                              const __half2* __restrict__ Vb2,
                                              int k0, int buf, int tid, int bn) {
    uint32_t abase = sb + buf * (AVA_ST * 4);
    #pragma unroll
    for (int j = 0; j < 2; j++) {
        int idx = tid + j * 256;     // 0..511
        int r   = idx >> 2;          // 0..127
        int c   = idx & 3;           // 16B chunk = 8 halves
        cp16(abase + (r * AVA_W + c * 4) * 4, Ab + (size_t)r * SEQ + k0 + c * 8);
    }
    uint32_t bbase = sb + (AV_NBUF * AVA_ST + buf * AVB_ST) * 4;
    const int k20 = k0 >> 1;
    #pragma unroll
    for (int j = 0; j < 2; j++) {
        int idx = tid + j * 256;     // 0..511
        int kr  = idx >> 5;          // 0..15
        int cc  = idx & 31;          // 16B chunk = 4 half2
        cp16(bbase + (kr * AVB_W + cc * 4) * 4, Vb2 + (size_t)(k20 + kr) * CH + bn + cc * 4);
    }
}

__global__ __launch_bounds__(256, 2)
void av_mma_kernel(const __half* __restrict__ P16, const __half2* __restrict__ V2,
                   const float* __restrict__ X, const float* __restrict__ gamma,
                   float* __restrict__ Out) {
    extern __shared__ float smemf[];
    uint32_t sb = smem_u32(smemf);
    const uint32_t* sw = (const uint32_t*)smemf;
    const int tid  = threadIdx.x;
    const int wid  = tid >> 5;
    const int lane = tid & 31;
    const int gid  = lane >> 2;
    const int tig  = lane & 3;
    const int wm   = (wid >> 2) * 64;
    const int wn   = (wid & 3) * 32;

    const int bz = blockIdx.z;
    const int bm = blockIdx.y * 128;
    const int bn = blockIdx.x * 128;
    const __half*  Ab  = P16 + ((size_t)bz * SEQ + bm) * SEQ;
    const __half2* Vb2 = V2 + (size_t)bz * (SEQ / 2) * CH;

    float acc[16][4];
    #pragma unroll
    for (int i = 0; i < 16; i++)
        #pragma unroll
        for (int j = 0; j < 4; j++) acc[i][j] = 0.f;

    av_load_stage(sb, Ab, Vb2, 0,  0, tid, bn); CP_COMMIT();
    av_load_stage(sb, Ab, Vb2, 32, 1, tid, bn); CP_COMMIT();
    av_load_stage(sb, Ab, Vb2, 64, 2, tid, bn); CP_COMMIT();

    const int NS = SEQ / 32;   // 128
    for (int s = 0; s < NS; s++) {
        const int buf = s % 3;
        if (s + 2 < NS)      { CP_WAIT_2(); }
        else if (s + 1 < NS) { CP_WAIT_1(); }
        else                 { CP_WAIT_0(); }
        __syncthreads();

        const uint32_t* As = sw + buf * AVA_ST;
        const uint32_t* Bs = sw + AV_NBUF * AVA_ST + buf * AVB_ST;

        #pragma unroll
        for (int ks = 0; ks < 2; ks++) {      // two k16 steps cover K=32
            uint32_t a[4][4], b[4][2];
            #pragma unroll
            for (int mt = 0; mt < 4; mt++) {
                int r = wm + mt * 16 + gid;
                a[mt][0] = As[r * AVA_W + ks * 8 + tig];
                a[mt][1] = As[(r + 8) * AVA_W + ks * 8 + tig];
                a[mt][2] = As[r * AVA_W + ks * 8 + tig + 4];
                a[mt][3] = As[(r + 8) * AVA_W + ks * 8 + tig + 4];
            }
            #pragma unroll
            for (int nt = 0; nt < 4; nt++) {
                int n = wn + nt * 8 + gid;
                b[nt][0] = Bs[(ks * 8 + tig) * AVB_W + n];
                b[nt][1] = Bs[(ks * 8 + tig + 4) * AVB_W + n];
            }
            #pragma unroll
            for (int mt = 0; mt < 4; mt++)
                #pragma unroll
                for (int nt = 0; nt < 4; nt++)
                    MMA_F16(acc[mt * 4 + nt], a[mt][0], a[mt][1], a[mt][2], a[mt][3],
                            b[nt][0], b[nt][1]);
        }
        __syncthreads();
        if (s + 3 < NS) {
            av_load_stage(sb, Ab, Vb2, (s + 3) * 32, buf, tid, bn);
            CP_COMMIT();
        }
    }

    const float g = gamma[0];
    #pragma unroll
    for (int mt = 0; mt < 4; mt++) {
        int r0 = bm + wm + mt * 16 + gid;
        size_t base0 = ((size_t)bz * SEQ + r0) * CH;
        size_t base1 = base0 + 8 * CH;
        #pragma unroll
        for (int nt = 0; nt < 4; nt++) {
            float* c = acc[mt * 4 + nt];
            int col = bn + wn + nt * 8 + 2 * tig;
            float2 x0 = *(const float2*)(X + base0 + col);
            float2 x1 = *(const float2*)(X + base1 + col);
            float2 o0, o1;
            o0.x = fmaf(g, c[0], x0.x); o0.y = fmaf(g, c[1], x0.y);
            o1.x = fmaf(g, c[2], x1.x); o1.y = fmaf(g, c[3], x1.y);
            *(float2*)(Out + base0 + col) = o0;
            *(float2*)(Out + base1 + col) = o1;
        }
    }
}

// ===========================================================================
extern "C" void kernel_launch(void* const* d_in, const int* in_sizes, int n_in,
                              void* d_out, int out_size) {
    const float* x     = (const float*)d_in[0];
    const float* Wq    = (const float*)d_in[1];
    const float* bq    = (const float*)d_in[2];
    const float* Wk    = (const float*)d_in[3];
    const float* bk    = (const float*)d_in[4];
    const float* Wv    = (const float*)d_in[5];
    const float* bv    = (const float*)d_in[6];
    const float* gamma = (const float*)d_in[7];

    float* out = (float*)d_out;                              // [B, N, C]
    float* att = out + (size_t)BATCH * SEQ * CH;             // [B, N, N]

    float *qh, *ql, *k, *kTh, *kTl;
    __half2* v2;
    __half* p16;
    cudaGetSymbolAddress((void**)&qh,  g_qh);
    cudaGetSymbolAddress((void**)&ql,  g_ql);
    cudaGetSymbolAddress((void**)&k,   g_k);
    cudaGetSymbolAddress((void**)&kTh, g_kTh);
    cudaGetSymbolAddress((void**)&kTl, g_kTl);
    cudaGetSymbolAddress((void**)&v2,  g_v2);
    cudaGetSymbolAddress((void**)&p16, g_p16);

    static bool attr_set = false;
    if (!attr_set) {
        cudaFuncSetAttribute(av_mma_kernel, cudaFuncAttributeMaxDynamicSharedMemorySize, AV_SMEM_BYTES);
        cudaFuncSetAttribute(energy_mma_kernel, cudaFuncAttributeMaxDynamicSharedMemorySize, E_SMEM_BYTES);
        attr_set = true;
    }

    const int M = BATCH * SEQ;  // 65536

    // Projections: q pre-split hi/lo; k plain (split+transposed below); v fp16 pair-interleaved
    proj_kernel<<<dim3(DIM / 64, M / 128), 256>>>(x, Wq, bq, qh, ql, nullptr, DIM);
    proj_kernel<<<dim3(DIM / 64, M / 128), 256>>>(x, Wk, bk, k, nullptr, nullptr, DIM);
    proj_kernel<<<dim3(CH  / 64, M / 128), 256>>>(x, Wv, bv, nullptr, nullptr, v2, CH);

    // k -> kT hi/lo (transpose + Dekker split)
    ksplit_kernel<<<dim3(DIM / 32, SEQ / 32, BATCH), dim3(32, 8)>>>(k, kTh, kTl);

    // Logits on tensor cores (pre-split operands)
    energy_mma_kernel<<<dim3(SEQ / 64, SEQ / 128, BATCH), 256, E_SMEM_BYTES>>>(qh, ql, kTh, kTl, att);

    // Row softmax: fp32 probs (full precision) + fp16 copy for AV
    softmax_kernel<<<M, 256>>>(att, p16);

    // attn @ V on fp16 m16n8k16 tensor cores, fused gamma-residual
    av_mma_kernel<<<dim3(CH / 128, SEQ / 128, BATCH), 256, AV_SMEM_BYTES>>>(p16, v2, x, gamma, out);
}

// round 14
// speedup vs baseline: 1.4025x; 1.1121x over previous
#include <cuda_runtime.h>
#include <cuda_fp16.h>
#include <cstdint>

#define BATCH 16
#define SEQ   4096
#define CH    512
#define DIM   64

// Scratch (allocation-free per harness rules)
__device__ __half  g_qh16[BATCH * SEQ * DIM];             // q hi fp16 [b,m,d]
__device__ __half  g_ql16[BATCH * SEQ * DIM];             // q lo fp16
__device__ float   g_k  [BATCH * SEQ * DIM];
__device__ __half2 g_kTh2[BATCH * (DIM / 2) * SEQ];       // kT hi pair-interleaved [b][d/2][n]
__device__ __half2 g_kTl2[BATCH * (DIM / 2) * SEQ];       // kT lo
__device__ __half2 g_v2[BATCH * (SEQ / 2) * CH];          // [b][k/2][n] pair-interleaved fp16
__device__ __half  g_p16[(size_t)BATCH * SEQ * SEQ];      // fp16 probs copy

// ===========================================================================
// helpers
// ===========================================================================
__device__ __forceinline__ uint32_t smem_u32(const void* p) {
    uint32_t a;
    asm("{ .reg .u64 t; cvta.to.shared.u64 t, %1; cvt.u32.u64 %0, t; }" : "=r"(a) : "l"(p));
    return a;
}
__device__ __forceinline__ void cp16(uint32_t dst, const void* src) {
    asm volatile("cp.async.cg.shared.global [%0], [%1], 16;" :: "r"(dst), "l"(src));
}
#define CP_COMMIT() asm volatile("cp.async.commit_group;" ::: "memory")
#define CP_WAIT_2() asm volatile("cp.async.wait_group 2;" ::: "memory")
#define CP_WAIT_1() asm volatile("cp.async.wait_group 1;" ::: "memory")
#define CP_WAIT_0() asm volatile("cp.async.wait_group 0;" ::: "memory")

#define MMA_F16(c, a0, a1, a2, a3, b0, b1) \
    asm volatile( \
        "mma.sync.aligned.m16n8k16.row.col.f32.f16.f16.f32 " \
        "{%0,%1,%2,%3}, {%4,%5,%6,%7}, {%8,%9}, {%0,%1,%2,%3};" \
        : "+f"((c)[0]), "+f"((c)[1]), "+f"((c)[2]), "+f"((c)[3]) \
        : "r"(a0), "r"(a1), "r"(a2), "r"(a3), "r"(b0), "r"(b1))

// ===========================================================================
// proj: C[M,N] = A[M,512] @ W[512,N] + bias.
// mode 0: fp32 out (k).  mode 1: fp16 hi/lo planes (q).  mode 2: fp16
// pair-interleaved [m/2][n] half2 (v).
// ===========================================================================
__global__ __launch_bounds__(256, 2)
void proj_kernel(const float* __restrict__ A, const float* __restrict__ W,
                 const float* __restrict__ bias, float* __restrict__ C,
                 __half* __restrict__ Ch, __half* __restrict__ Cl,
                 __half2* __restrict__ C2, int N, int mode) {
    const int K = CH;
    __shared__ float As[32][132];
    __shared__ float Ws[32][64];
    const int bm = blockIdx.y * 128;
    const int bn = blockIdx.x * 64;
    const int tid = threadIdx.x;
    const int tn = tid & 15;
    const int tm = tid >> 4;
    float acc[8][4] = {};

    for (int k0 = 0; k0 < K; k0 += 32) {
        #pragma unroll
        for (int i = 0; i < 4; i++) {
            int fidx = tid + i * 256;
            int row  = fidx >> 3;
            int kc   = (fidx & 7) * 4;
            float4 t = *(const float4*)(A + (size_t)(bm + row) * K + k0 + kc);
            As[kc + 0][row] = t.x; As[kc + 1][row] = t.y;
            As[kc + 2][row] = t.z; As[kc + 3][row] = t.w;
        }
        #pragma unroll
        for (int i = 0; i < 2; i++) {
            int fidx = tid + i * 256;
            int kr   = fidx >> 4;
            int nc   = (fidx & 15) * 4;
            *(float4*)&Ws[kr][nc] = *(const float4*)(W + (size_t)(k0 + kr) * N + bn + nc);
        }
        __syncthreads();
        #pragma unroll
        for (int kk = 0; kk < 32; kk++) {
            float4 a0 = *(const float4*)&As[kk][tm * 8];
            float4 a1 = *(const float4*)&As[kk][tm * 8 + 4];
            float4 w0 = *(const float4*)&Ws[kk][tn * 4];
            float a[8] = {a0.x, a0.y, a0.z, a0.w, a1.x, a1.y, a1.z, a1.w};
            float w[4] = {w0.x, w0.y, w0.z, w0.w};
            #pragma unroll
            for (int i = 0; i < 8; i++)
                #pragma unroll
                for (int j = 0; j < 4; j++)
                    acc[i][j] = fmaf(a[i], w[j], acc[i][j]);
        }
        __syncthreads();
    }
    if (mode == 2) {
        // fp16 pair-interleaved: half2 at [row/2][col] = (v[row], v[row+1])
        #pragma unroll
        for (int i = 0; i < 8; i += 2) {
            size_t row2 = (size_t)(bm + tm * 8 + i) >> 1;
            #pragma unroll
            for (int j = 0; j < 4; j++) {
                int col = bn + tn * 4 + j;
                float lo = acc[i][j]     + bias[col];
                float hi = acc[i + 1][j] + bias[col];
                C2[row2 * N + col] = __floats2half2_rn(lo, hi);
            }
        }
        return;
    }
    if (mode == 1) {
        // fp16 Dekker hi/lo planes, row-major [m][N]
        #pragma unroll
        for (int i = 0; i < 8; i++) {
            size_t row = bm + tm * 8 + i;
            int col = bn + tn * 4;
            float v0 = acc[i][0] + bias[col + 0];
            float v1 = acc[i][1] + bias[col + 1];
            float v2 = acc[i][2] + bias[col + 2];
            float v3 = acc[i][3] + bias[col + 3];
            __half h0 = __float2half_rn(v0), h1 = __float2half_rn(v1);
            __half h2 = __float2half_rn(v2), h3 = __float2half_rn(v3);
            __half l0 = __float2half_rn(v0 - __half2float(h0));
            __half l1 = __float2half_rn(v1 - __half2float(h1));
            __half l2 = __float2half_rn(v2 - __half2float(h2));
            __half l3 = __float2half_rn(v3 - __half2float(h3));
            __half2* ph = (__half2*)(Ch + row * N + col);
            __half2* pl = (__half2*)(Cl + row * N + col);
            ph[0] = __halves2half2(h0, h1); ph[1] = __halves2half2(h2, h3);
            pl[0] = __halves2half2(l0, l1); pl[1] = __halves2half2(l2, l3);
        }
        return;
    }
    #pragma unroll
    for (int i = 0; i < 8; i++) {
        size_t row = bm + tm * 8 + i;
        int col = bn + tn * 4;
        float4 o;
        o.x = acc[i][0] + bias[col + 0];
        o.y = acc[i][1] + bias[col + 1];
        o.z = acc[i][2] + bias[col + 2];
        o.w = acc[i][3] + bias[col + 3];
        *(float4*)(C + row * N + col) = o;
    }
}

// ===========================================================================
// ksplit: k[b,n,d] fp32 -> kT hi/lo fp16 pair-interleaved [b][d/2][n]
// ===========================================================================
__global__ __launch_bounds__(256)
void ksplit_kernel(const float* __restrict__ K, __half2* __restrict__ KTh2,
                   __half2* __restrict__ KTl2) {
    __shared__ float t[32][33];
    const int b  = blockIdx.z;
    const int d0 = blockIdx.x * 32;
    const int n0 = blockIdx.y * 32;
    const float* Kb = K + (size_t)b * SEQ * DIM;
    const size_t tb2 = (size_t)b * (DIM / 2) * SEQ;
    const int tx = threadIdx.x, ty = threadIdx.y;
    #pragma unroll
    for (int j = 0; j < 4; j++)
        t[ty + j * 8][tx] = Kb[(size_t)(n0 + ty + j * 8) * DIM + d0 + tx];
    __syncthreads();
    // t[n_loc][d_loc]; produce pair rows (d, d+1)
    #pragma unroll
    for (int j = 0; j < 2; j++) {
        int d2loc = ty + j * 8;          // 0..15
        float v0 = t[tx][2 * d2loc];
        float v1 = t[tx][2 * d2loc + 1];
        __half h0 = __float2half_rn(v0), h1 = __float2half_rn(v1);
        __half l0 = __float2half_rn(v0 - __half2float(h0));
        __half l1 = __float2half_rn(v1 - __half2float(h1));
        size_t off = tb2 + (size_t)(d0 / 2 + d2loc) * SEQ + n0 + tx;
        KTh2[off] = __halves2half2(h0, h1);
        KTl2[off] = __halves2half2(l0, l1);
    }
}

// ===========================================================================
// energy_mma: E[b,m,n] = QK^T on fp16 m16n8k16 tensor cores, Dekker hi/lo
// (hh + hl + lh).  128m x 64n tile, K=64 whole reduction, 8 warps of
// 64m x 16n, 2 CTAs/SM.
// A: fp16 [128][64] word-stride 36 (hi, lo).  B: half2 [32 k2][64 n]
// word-stride 72 (hi, lo).
// ===========================================================================
#define E16_AH 0
#define E16_AL 4608                      // 128*36
#define E16_KH 9216
#define E16_KL 11520                     // +32*72
#define E16_SMEM_W 13824
#define E16_SMEM_BYTES (E16_SMEM_W * 4)  // 55296

__global__ __launch_bounds__(256, 2)
void energy_mma_kernel(const __half* __restrict__ Qh, const __half* __restrict__ Ql,
                       const __half2* __restrict__ KTh2, const __half2* __restrict__ KTl2,
                       float* __restrict__ E) {
    extern __shared__ float smemf[];
    uint32_t sb = smem_u32(smemf);
    const uint32_t* sw = (const uint32_t*)smemf;

    const int tid  = threadIdx.x;
    const int wid  = tid >> 5;
    const int lane = tid & 31;
    const int gid  = lane >> 2;      // 0..7
    const int tig  = lane & 3;       // 0..3
    const int wm   = (wid >> 2) * 64;    // 0 or 64
    const int wn   = (wid & 3) * 16;     // 0,16,32,48

    const int bz = blockIdx.z;
    const int bm = blockIdx.y * 128;
    const int bn = blockIdx.x * 64;
    const __half* Qhb = Qh + ((size_t)bz * SEQ + bm) * DIM;
    const __half* Qlb = Ql + ((size_t)bz * SEQ + bm) * DIM;
    const __half2* KThb = KTh2 + (size_t)bz * (DIM / 2) * SEQ + bn;
    const __half2* KTlb = KTl2 + (size_t)bz * (DIM / 2) * SEQ + bn;
    float* Eb = E + (size_t)bz * SEQ * SEQ;

    // A hi/lo: 128 rows x 8 chunks (16B = 8 halves), word-stride 36
    #pragma unroll
    for (int j = 0; j < 4; j++) {
        int idx = tid + j * 256;     // 0..1023
        int r   = idx >> 3;          // 0..127
        int c   = idx & 7;
        cp16(sb + (uint32_t)(E16_AH + r * 36 + c * 4) * 4, Qhb + (size_t)r * DIM + c * 8);
        cp16(sb + (uint32_t)(E16_AL + r * 36 + c * 4) * 4, Qlb + (size_t)r * DIM + c * 8);
    }
    // K hi/lo: 32 k2-rows x 16 chunks (16B = 4 half2), word-stride 72
    #pragma unroll
    for (int j = 0; j < 2; j++) {
        int idx = tid + j * 256;     // 0..511
        int r   = idx >> 4;          // 0..31
        int c   = idx & 15;
        cp16(sb + (uint32_t)(E16_KH + r * 72 + c * 4) * 4, KThb + (size_t)r * SEQ + c * 4);
        cp16(sb + (uint32_t)(E16_KL + r * 72 + c * 4) * 4, KTlb + (size_t)r * SEQ + c * 4);
    }
    CP_COMMIT();
    CP_WAIT_0();
    __syncthreads();

    float acc[8][4];
    #pragma unroll
    for (int i = 0; i < 8; i++)
        #pragma unroll
        for (int j = 0; j < 4; j++) acc[i][j] = 0.f;

    #pragma unroll
    for (int ks = 0; ks < 4; ks++) {     // four k16 steps cover K=64
        uint32_t ah[4][4], al[4][4], bh[2][2], bl[2][2];
        #pragma unroll
        for (int mt = 0; mt < 4; mt++) {
            int r = wm + mt * 16 + gid;
            ah[mt][0] = sw[E16_AH + r * 36 + ks * 8 + tig];
            ah[mt][1] = sw[E16_AH + (r + 8) * 36 + ks * 8 + tig];
            ah[mt][2] = sw[E16_AH + r * 36 + ks * 8 + tig + 4];
            ah[mt][3] = sw[E16_AH + (r + 8) * 36 + ks * 8 + tig + 4];
            al[mt][0] = sw[E16_AL + r * 36 + ks * 8 + tig];
            al[mt][1] = sw[E16_AL + (r + 8) * 36 + ks * 8 + tig];
            al[mt][2] = sw[E16_AL + r * 36 + ks * 8 + tig + 4];
            al[mt][3] = sw[E16_AL + (r + 8) * 36 + ks * 8 + tig + 4];
        }
        #pragma unroll
        for (int nt = 0; nt < 2; nt++) {
            int n = wn + nt * 8 + gid;
            bh[nt][0] = sw[E16_KH + (ks * 8 + tig) * 72 + n];
            bh[nt][1] = sw[E16_KH + (ks * 8 + tig + 4) * 72 + n];
            bl[nt][0] = sw[E16_KL + (ks * 8 + tig) * 72 + n];
            bl[nt][1] = sw[E16_KL + (ks * 8 + tig + 4) * 72 + n];
        }
        #pragma unroll
        for (int mt = 0; mt < 4; mt++)
            #pragma unroll
            for (int nt = 0; nt < 2; nt++)
                MMA_F16(acc[mt * 2 + nt], ah[mt][0], ah[mt][1], ah[mt][2], ah[mt][3],
                        bh[nt][0], bh[nt][1]);
        #pragma unroll
        for (int mt = 0; mt < 4; mt++)
            #pragma unroll
            for (int nt = 0; nt < 2; nt++)
                MMA_F16(acc[mt * 2 + nt], ah[mt][0], ah[mt][1], ah[mt][2], ah[mt][3],
                        bl[nt][0], bl[nt][1]);
        #pragma unroll
        for (int mt = 0; mt < 4; mt++)
            #pragma unroll
            for (int nt = 0; nt < 2; nt++)
                MMA_F16(acc[mt * 2 + nt], al[mt][0], al[mt][1], al[mt][2], al[mt][3],
                        bh[nt][0], bh[nt][1]);
    }

    #pragma unroll
    for (int mt = 0; mt < 4; mt++) {
        int r0 = bm + wm + mt * 16 + gid;
        size_t base0 = (size_t)r0 * SEQ;
        size_t base1 = base0 + 8 * SEQ;
        #pragma unroll
        for (int nt = 0; nt < 2; nt++) {
            float* c = acc[mt * 2 + nt];
            int col = bn + wn + nt * 8 + 2 * tig;
            *(float2*)(Eb + base0 + col) = make_float2(c[0], c[1]);
            *(float2*)(Eb + base1 + col) = make_float2(c[2], c[3]);
        }
    }
}

// ===========================================================================
// softmax: in-place row softmax. fp32 probs to E + fp16 copy to P16.
// ===========================================================================
__global__ __launch_bounds__(256)
void softmax_kernel(float* __restrict__ E, __half* __restrict__ P16) {
    const int tid = threadIdx.x;
    const size_t base = (size_t)blockIdx.x * SEQ;
    float4* p = (float4*)(E + base);
    float4 v[4];
    float mx = -3.4e38f;
    #pragma unroll
    for (int i = 0; i < 4; i++) {
        v[i] = p[tid + i * 256];
        mx = fmaxf(mx, fmaxf(fmaxf(v[i].x, v[i].y), fmaxf(v[i].z, v[i].w)));
    }
    __shared__ float sred[8];
    #pragma unroll
    for (int o = 16; o > 0; o >>= 1) mx = fmaxf(mx, __shfl_xor_sync(0xffffffffu, mx, o));
    if ((tid & 31) == 0) sred[tid >> 5] = mx;
    __syncthreads();
    if (tid == 0) {
        float m = sred[0];
        #pragma unroll
        for (int i = 1; i < 8; i++) m = fmaxf(m, sred[i]);
        sred[0] = m;
    }
    __syncthreads();
    mx = sred[0];
    __syncthreads();

    float s = 0.f;
    #pragma unroll
    for (int i = 0; i < 4; i++) {
        v[i].x = __expf(v[i].x - mx);
        v[i].y = __expf(v[i].y - mx);
        v[i].z = __expf(v[i].z - mx);
        v[i].w = __expf(v[i].w - mx);
        s += (v[i].x + v[i].y) + (v[i].z + v[i].w);
    }
    #pragma unroll
    for (int o = 16; o > 0; o >>= 1) s += __shfl_xor_sync(0xffffffffu, s, o);
    if ((tid & 31) == 0) sred[tid >> 5] = s;
    __syncthreads();
    if (tid == 0) {
        float t = 0.f;
        #pragma unroll
        for (int i = 0; i < 8; i++) t += sred[i];
        sred[0] = t;
    }
    __syncthreads();
    float inv = 1.0f / sred[0];
    #pragma unroll
    for (int i = 0; i < 4; i++) {
        v[i].x *= inv; v[i].y *= inv; v[i].z *= inv; v[i].w *= inv;
        p[tid + i * 256] = v[i];
        __half2 h01 = __floats2half2_rn(v[i].x, v[i].y);
        __half2 h23 = __floats2half2_rn(v[i].z, v[i].w);
        uint2 pk;
        pk.x = *(uint32_t*)&h01;
        pk.y = *(uint32_t*)&h23;
        *(uint2*)(P16 + base + (size_t)(tid + i * 256) * 4) = pk;
    }
}

// ===========================================================================
// av_mma: Out = gamma * (Att @ V) + X on fp16 m16n8k16 tensor cores.
// Block 128x128, stage K=64 (4 k16 steps), 8 warps of 64x32, 3-stage
// cp.async pipeline.
// A: fp16 probs [128][64], word-stride 36.  B: half2 [32 k2][128 n],
// word-stride 136.
// ===========================================================================
#define AVA_W 36
#define AVB_W 136
#define AVA_ST (128 * AVA_W)     // 4608 words
#define AVB_ST (32 * AVB_W)      // 4352 words
#define AV_NBUF 3
#define AV_SMEM_W (AV_NBUF * (AVA_ST + AVB_ST))   // 26880 words
#define AV_SMEM_BYTES (AV_SMEM_W * 4)             // 107520

__device__ __forceinline__ void av_load_stage(uint32_t sb, const __half* __restrict__ Ab,
                                              const __half2* __restrict__ Vb2,
                                              int k0, int buf, int tid, int bn) {
    uint32_t abase = sb + buf * (AVA_ST * 4);
    #pragma unroll
    for (int j = 0; j < 4; j++) {
        int idx = tid + j * 256;     // 0..1023
        int r   = idx >> 3;          // 0..127
        int c   = idx & 7;           // 16B chunk = 8 halves
        cp16(abase + (r * AVA_W + c * 4) * 4, Ab + (size_t)r * SEQ + k0 + c * 8);
    }
    uint32_t bbase = sb + (AV_NBUF * AVA_ST + buf * AVB_ST) * 4;
    const int k20 = k0 >> 1;
    #pragma unroll
    for (int j = 0; j < 4; j++) {
        int idx = tid + j * 256;     // 0..1023
        int kr  = idx >> 5;          // 0..31
        int cc  = idx & 31;          // 16B chunk = 4 half2
        cp16(bbase + (kr * AVB_W + cc * 4) * 4, Vb2 + (size_t)(k20 + kr) * CH + bn + cc * 4);
    }
}

__global__ __launch_bounds__(256, 2)
void av_mma_kernel(const __half* __restrict__ P16, const __half2* __restrict__ V2,
                   const float* __restrict__ X, const float* __restrict__ gamma,
                   float* __restrict__ Out) {
    extern __shared__ float smemf[];
    uint32_t sb = smem_u32(smemf);
    const uint32_t* sw = (const uint32_t*)smemf;
    const int tid  = threadIdx.x;
    const int wid  = tid >> 5;
    const int lane = tid & 31;
    const int gid  = lane >> 2;
    const int tig  = lane & 3;
    const int wm   = (wid >> 2) * 64;
    const int wn   = (wid & 3) * 32;

    const int bz = blockIdx.z;
    const int bm = blockIdx.y * 128;
    const int bn = blockIdx.x * 128;
    const __half*  Ab  = P16 + ((size_t)bz * SEQ + bm) * SEQ;
    const __half2* Vb2 = V2 + (size_t)bz * (SEQ / 2) * CH;

    float acc[16][4];
    #pragma unroll
    for (int i = 0; i < 16; i++)
        #pragma unroll
        for (int j = 0; j < 4; j++) acc[i][j] = 0.f;

    av_load_stage(sb, Ab, Vb2, 0,   0, tid, bn); CP_COMMIT();
    av_load_stage(sb, Ab, Vb2, 64,  1, tid, bn); CP_COMMIT();
    av_load_stage(sb, Ab, Vb2, 128, 2, tid, bn); CP_COMMIT();

    const int NS = SEQ / 64;   // 64
    for (int s = 0; s < NS; s++) {
        const int buf = s % 3;
        if (s + 2 < NS)      { CP_WAIT_2(); }
        else if (s + 1 < NS) { CP_WAIT_1(); }
        else                 { CP_WAIT_0(); }
        __syncthreads();

        const uint32_t* As = sw + buf * AVA_ST;
        const uint32_t* Bs = sw + AV_NBUF * AVA_ST + buf * AVB_ST;

        #pragma unroll
        for (int ks = 0; ks < 4; ks++) {      // four k16 steps cover K=64
            uint32_t a[4][4], b[4][2];
            #pragma unroll
            for (int mt = 0; mt < 4; mt++) {
                int r = wm + mt * 16 + gid;
                a[mt][0] = As[r * AVA_W + ks * 8 + tig];
                a[mt][1] = As[(r + 8) * AVA_W + ks * 8 + tig];
                a[mt][2] = As[r * AVA_W + ks * 8 + tig + 4];
                a[mt][3] = As[(r + 8) * AVA_W + ks * 8 + tig + 4];
            }
            #pragma unroll
            for (int nt = 0; nt < 4; nt++) {
                int n = wn + nt * 8 + gid;
                b[nt][0] = Bs[(ks * 8 + tig) * AVB_W + n];
                b[nt][1] = Bs[(ks * 8 + tig + 4) * AVB_W + n];
            }
            #pragma unroll
            for (int mt = 0; mt < 4; mt++)
                #pragma unroll
                for (int nt = 0; nt < 4; nt++)
                    MMA_F16(acc[mt * 4 + nt], a[mt][0], a[mt][1], a[mt][2], a[mt][3],
                            b[nt][0], b[nt][1]);
        }
        __syncthreads();
        if (s + 3 < NS) {
            av_load_stage(sb, Ab, Vb2, (s + 3) * 64, buf, tid, bn);
            CP_COMMIT();
        }
    }

    const float g = gamma[0];
    #pragma unroll
    for (int mt = 0; mt < 4; mt++) {
        int r0 = bm + wm + mt * 16 + gid;
        size_t base0 = ((size_t)bz * SEQ + r0) * CH;
        size_t base1 = base0 + 8 * CH;
        #pragma unroll
        for (int nt = 0; nt < 4; nt++) {
            float* c = acc[mt * 4 + nt];
            int col = bn + wn + nt * 8 + 2 * tig;
            float2 x0 = *(const float2*)(X + base0 + col);
            float2 x1 = *(const float2*)(X + base1 + col);
            float2 o0, o1;
            o0.x = fmaf(g, c[0], x0.x); o0.y = fmaf(g, c[1], x0.y);
            o1.x = fmaf(g, c[2], x1.x); o1.y = fmaf(g, c[3], x1.y);
            *(float2*)(Out + base0 + col) = o0;
            *(float2*)(Out + base1 + col) = o1;
        }
    }
}

// ===========================================================================
extern "C" void kernel_launch(void* const* d_in, const int* in_sizes, int n_in,
                              void* d_out, int out_size) {
    const float* x     = (const float*)d_in[0];
    const float* Wq    = (const float*)d_in[1];
    const float* bq    = (const float*)d_in[2];
    const float* Wk    = (const float*)d_in[3];
    const float* bk    = (const float*)d_in[4];
    const float* Wv    = (const float*)d_in[5];
    const float* bv    = (const float*)d_in[6];
    const float* gamma = (const float*)d_in[7];

    float* out = (float*)d_out;                              // [B, N, C]
    float* att = out + (size_t)BATCH * SEQ * CH;             // [B, N, N]

    __half *qh16, *ql16, *p16;
    float *k;
    __half2 *kTh2, *kTl2, *v2;
    cudaGetSymbolAddress((void**)&qh16, g_qh16);
    cudaGetSymbolAddress((void**)&ql16, g_ql16);
    cudaGetSymbolAddress((void**)&k,    g_k);
    cudaGetSymbolAddress((void**)&kTh2, g_kTh2);
    cudaGetSymbolAddress((void**)&kTl2, g_kTl2);
    cudaGetSymbolAddress((void**)&v2,   g_v2);
    cudaGetSymbolAddress((void**)&p16,  g_p16);

    static bool attr_set = false;
    if (!attr_set) {
        cudaFuncSetAttribute(av_mma_kernel, cudaFuncAttributeMaxDynamicSharedMemorySize, AV_SMEM_BYTES);
        cudaFuncSetAttribute(energy_mma_kernel, cudaFuncAttributeMaxDynamicSharedMemorySize, E16_SMEM_BYTES);
        attr_set = true;
    }

    const int M = BATCH * SEQ;  // 65536

    // Projections: q fp16 hi/lo planes; k fp32 (split below); v fp16 pair-interleaved
    proj_kernel<<<dim3(DIM / 64, M / 128), 256>>>(x, Wq, bq, nullptr, qh16, ql16, nullptr, DIM, 1);
    proj_kernel<<<dim3(DIM / 64, M / 128), 256>>>(x, Wk, bk, k, nullptr, nullptr, nullptr, DIM, 0);
    proj_kernel<<<dim3(CH  / 64, M / 128), 256>>>(x, Wv, bv, nullptr, nullptr, nullptr, v2, CH, 2);

    // k -> kT hi/lo fp16 pair-interleaved (transpose + Dekker split)
    ksplit_kernel<<<dim3(DIM / 32, SEQ / 32, BATCH), dim3(32, 8)>>>(k, kTh2, kTl2);

    // Logits on fp16 tensor cores (Dekker hh+hl+lh)
    energy_mma_kernel<<<dim3(SEQ / 64, SEQ / 128, BATCH), 256, E16_SMEM_BYTES>>>(qh16, ql16, kTh2, kTl2, att);

    // Row softmax: fp32 probs (checked output) + fp16 copy for AV
    softmax_kernel<<<M, 256>>>(att, p16);

    // attn @ V on fp16 tensor cores, K=64 stages, fused gamma-residual
    av_mma_kernel<<<dim3(CH / 128, SEQ / 128, BATCH), 256, AV_SMEM_BYTES>>>(p16, v2, x, gamma, out);
}

// round 15
// speedup vs baseline: 1.4085x; 1.0043x over previous
#include <cuda_runtime.h>
#include <cuda_fp16.h>
#include <cstdint>

#define BATCH 16
#define SEQ   4096
#define CH    512
#define DIM   64

// Scratch (allocation-free per harness rules)
__device__ __half  g_qh16[BATCH * SEQ * DIM];             // q hi fp16 [b,m,d]
__device__ __half  g_ql16[BATCH * SEQ * DIM];             // q lo fp16
__device__ __half2 g_kh2[BATCH * SEQ * (DIM / 2)];        // k hi pair-interleaved [b][n][d2]
__device__ __half2 g_kl2[BATCH * SEQ * (DIM / 2)];        // k lo
__device__ float   g_v [BATCH * SEQ * CH];                // v fp32 [b][n][ch]
__device__ __half2 g_v2T[BATCH * CH * (SEQ / 2)];         // v fp16 pair-interleaved [b][ch][seq2]
__device__ __half  g_p16[(size_t)BATCH * SEQ * SEQ];      // fp16 probs copy

// ===========================================================================
// helpers
// ===========================================================================
__device__ __forceinline__ uint32_t smem_u32(const void* p) {
    uint32_t a;
    asm("{ .reg .u64 t; cvta.to.shared.u64 t, %1; cvt.u32.u64 %0, t; }" : "=r"(a) : "l"(p));
    return a;
}
__device__ __forceinline__ void cp16(uint32_t dst, const void* src) {
    asm volatile("cp.async.cg.shared.global [%0], [%1], 16;" :: "r"(dst), "l"(src));
}
#define CP_COMMIT() asm volatile("cp.async.commit_group;" ::: "memory")
#define CP_WAIT_2() asm volatile("cp.async.wait_group 2;" ::: "memory")
#define CP_WAIT_1() asm volatile("cp.async.wait_group 1;" ::: "memory")
#define CP_WAIT_0() asm volatile("cp.async.wait_group 0;" ::: "memory")

#define MMA_F16(c, a0, a1, a2, a3, b0, b1) \
    asm volatile( \
        "mma.sync.aligned.m16n8k16.row.col.f32.f16.f16.f32 " \
        "{%0,%1,%2,%3}, {%4,%5,%6,%7}, {%8,%9}, {%0,%1,%2,%3};" \
        : "+f"((c)[0]), "+f"((c)[1]), "+f"((c)[2]), "+f"((c)[3]) \
        : "r"(a0), "r"(a1), "r"(a2), "r"(a3), "r"(b0), "r"(b1))

#define LDSM_X4(r, addr) \
    asm volatile("ldmatrix.sync.aligned.m8n8.x4.shared.b16 {%0,%1,%2,%3}, [%4];" \
        : "=r"((r)[0]), "=r"((r)[1]), "=r"((r)[2]), "=r"((r)[3]) : "r"(addr))

// ===========================================================================
// proj: C[M,N] = A[M,512] @ W[512,N] + bias.
// mode 0: fp32 out (v).  mode 1: fp16 hi/lo planes (q).
// mode 3: fp16 hi/lo pair-interleaved [m][N/2] half2 (k, pairs along N).
// ===========================================================================
__global__ __launch_bounds__(256, 2)
void proj_kernel(const float* __restrict__ A, const float* __restrict__ W,
                 const float* __restrict__ bias, float* __restrict__ C,
                 __half* __restrict__ Ch, __half* __restrict__ Cl,
                 __half2* __restrict__ Ch2, __half2* __restrict__ Cl2,
                 int N, int mode) {
    const int K = CH;
    __shared__ float As[32][132];
    __shared__ float Ws[32][64];
    const int bm = blockIdx.y * 128;
    const int bn = blockIdx.x * 64;
    const int tid = threadIdx.x;
    const int tn = tid & 15;
    const int tm = tid >> 4;
    float acc[8][4] = {};

    for (int k0 = 0; k0 < K; k0 += 32) {
        #pragma unroll
        for (int i = 0; i < 4; i++) {
            int fidx = tid + i * 256;
            int row  = fidx >> 3;
            int kc   = (fidx & 7) * 4;
            float4 t = *(const float4*)(A + (size_t)(bm + row) * K + k0 + kc);
            As[kc + 0][row] = t.x; As[kc + 1][row] = t.y;
            As[kc + 2][row] = t.z; As[kc + 3][row] = t.w;
        }
        #pragma unroll
        for (int i = 0; i < 2; i++) {
            int fidx = tid + i * 256;
            int kr   = fidx >> 4;
            int nc   = (fidx & 15) * 4;
            *(float4*)&Ws[kr][nc] = *(const float4*)(W + (size_t)(k0 + kr) * N + bn + nc);
        }
        __syncthreads();
        #pragma unroll
        for (int kk = 0; kk < 32; kk++) {
            float4 a0 = *(const float4*)&As[kk][tm * 8];
            float4 a1 = *(const float4*)&As[kk][tm * 8 + 4];
            float4 w0 = *(const float4*)&Ws[kk][tn * 4];
            float a[8] = {a0.x, a0.y, a0.z, a0.w, a1.x, a1.y, a1.z, a1.w};
            float w[4] = {w0.x, w0.y, w0.z, w0.w};
            #pragma unroll
            for (int i = 0; i < 8; i++)
                #pragma unroll
                for (int j = 0; j < 4; j++)
                    acc[i][j] = fmaf(a[i], w[j], acc[i][j]);
        }
        __syncthreads();
    }
    if (mode == 3) {
        // fp16 hi/lo pair-interleaved along N: word (m, n2) = halves(v[2n2], v[2n2+1])
        const int N2 = N >> 1;
        #pragma unroll
        for (int i = 0; i < 8; i++) {
            size_t row = bm + tm * 8 + i;
            int col = bn + tn * 4;
            float v0 = acc[i][0] + bias[col + 0];
            float v1 = acc[i][1] + bias[col + 1];
            float v2 = acc[i][2] + bias[col + 2];
            float v3 = acc[i][3] + bias[col + 3];
            __half h0 = __float2half_rn(v0), h1 = __float2half_rn(v1);
            __half h2 = __float2half_rn(v2), h3 = __float2half_rn(v3);
            __half l0 = __float2half_rn(v0 - __half2float(h0));
            __half l1 = __float2half_rn(v1 - __half2float(h1));
            __half l2 = __float2half_rn(v2 - __half2float(h2));
            __half l3 = __float2half_rn(v3 - __half2float(h3));
            size_t off = row * N2 + (col >> 1);
            Ch2[off]     = __halves2half2(h0, h1);
            Ch2[off + 1] = __halves2half2(h2, h3);
            Cl2[off]     = __halves2half2(l0, l1);
            Cl2[off + 1] = __halves2half2(l2, l3);
        }
        return;
    }
    if (mode == 1) {
        #pragma unroll
        for (int i = 0; i < 8; i++) {
            size_t row = bm + tm * 8 + i;
            int col = bn + tn * 4;
            float v0 = acc[i][0] + bias[col + 0];
            float v1 = acc[i][1] + bias[col + 1];
            float v2 = acc[i][2] + bias[col + 2];
            float v3 = acc[i][3] + bias[col + 3];
            __half h0 = __float2half_rn(v0), h1 = __float2half_rn(v1);
            __half h2 = __float2half_rn(v2), h3 = __float2half_rn(v3);
            __half l0 = __float2half_rn(v0 - __half2float(h0));
            __half l1 = __float2half_rn(v1 - __half2float(h1));
            __half l2 = __float2half_rn(v2 - __half2float(h2));
            __half l3 = __float2half_rn(v3 - __half2float(h3));
            __half2* ph = (__half2*)(Ch + row * N + col);
            __half2* pl = (__half2*)(Cl + row * N + col);
            ph[0] = __halves2half2(h0, h1); ph[1] = __halves2half2(h2, h3);
            pl[0] = __halves2half2(l0, l1); pl[1] = __halves2half2(l2, l3);
        }
        return;
    }
    #pragma unroll
    for (int i = 0; i < 8; i++) {
        size_t row = bm + tm * 8 + i;
        int col = bn + tn * 4;
        float4 o;
        o.x = acc[i][0] + bias[col + 0];
        o.y = acc[i][1] + bias[col + 1];
        o.z = acc[i][2] + bias[col + 2];
        o.w = acc[i][3] + bias[col + 3];
        *(float4*)(C + row * N + col) = o;
    }
}

// ===========================================================================
// vsplit: v[b,n,ch] fp32 -> v2T[b][ch][n/2] half2 (pairs along n)
// ===========================================================================
__global__ __launch_bounds__(256)
void vsplit_kernel(const float* __restrict__ V, __half2* __restrict__ V2T) {
    __shared__ float t[32][33];
    const int b  = blockIdx.z;
    const int n0 = blockIdx.y * 32;
    const int c0 = blockIdx.x * 32;
    const float* Vb = V + (size_t)b * SEQ * CH;
    __half2* Tb = V2T + (size_t)b * CH * (SEQ / 2);
    const int tid = threadIdx.x;
    #pragma unroll
    for (int j = 0; j < 4; j++) {
        int idx = tid + j * 256;     // 0..1023
        int r = idx >> 5;            // n row 0..31
        int c = idx & 31;            // ch 0..31
        t[r][c] = Vb[(size_t)(n0 + r) * CH + c0 + c];
    }
    __syncthreads();
    #pragma unroll
    for (int j = 0; j < 2; j++) {
        int idx = tid + j * 256;     // 0..511
        int ch = idx >> 4;           // 0..31
        int n2 = idx & 15;           // 0..15
        Tb[(size_t)(c0 + ch) * (SEQ / 2) + (n0 >> 1) + n2] =
            __floats2half2_rn(t[2 * n2][ch], t[2 * n2 + 1][ch]);
    }
}

// ===========================================================================
// energy_mma: E = QK^T on fp16 m16n8k16 (Dekker hh+hl+lh), ldmatrix loads.
// 128m x 64n tile, K=64 whole reduction, 8 warps of 64m x 16n, 2 CTAs/SM.
// A: fp16 [128][64] word-stride 36 (hi, lo planes).
// B: half2 [64 n][32 d2] word-stride 36 (hi, lo planes), n-major.
// ===========================================================================
#define E16_AH 0
#define E16_AL 4608                      // 128*36
#define E16_KH 9216
#define E16_KL 11520                     // +64*36
#define E16_SMEM_W 13824
#define E16_SMEM_BYTES (E16_SMEM_W * 4)  // 55296

__global__ __launch_bounds__(256, 2)
void energy_mma_kernel(const __half* __restrict__ Qh, const __half* __restrict__ Ql,
                       const __half2* __restrict__ Kh2, const __half2* __restrict__ Kl2,
                       float* __restrict__ E) {
    extern __shared__ float smemf[];
    uint32_t sb = smem_u32(smemf);

    const int tid  = threadIdx.x;
    const int wid  = tid >> 5;
    const int lane = tid & 31;
    const int gid  = lane >> 2;
    const int tig  = lane & 3;
    const int wm   = (wid >> 2) * 64;    // 0 or 64
    const int wn   = (wid & 3) * 16;     // 0,16,32,48

    // ldmatrix lane-derived offsets
    const int a_ro = ((lane >> 3) & 1) * 8 + (lane & 7);
    const int a_co = (lane >> 4) * 4;
    const int b_ro = (lane >> 4) * 8 + (lane & 7);
    const int b_co = ((lane >> 3) & 1) * 4;

    const int bz = blockIdx.z;
    const int bm = blockIdx.y * 128;
    const int bn = blockIdx.x * 64;
    const __half* Qhb = Qh + ((size_t)bz * SEQ + bm) * DIM;
    const __half* Qlb = Ql + ((size_t)bz * SEQ + bm) * DIM;
    const __half2* Khb = Kh2 + ((size_t)bz * SEQ + bn) * (DIM / 2);
    const __half2* Klb = Kl2 + ((size_t)bz * SEQ + bn) * (DIM / 2);
    float* Eb = E + (size_t)bz * SEQ * SEQ;

    // A hi/lo: 128 rows x 8 chunks (16B = 8 halves), word-stride 36
    #pragma unroll
    for (int j = 0; j < 4; j++) {
        int idx = tid + j * 256;
        int r   = idx >> 3;
        int c   = idx & 7;
        cp16(sb + (uint32_t)(E16_AH + r * 36 + c * 4) * 4, Qhb + (size_t)r * DIM + c * 8);
        cp16(sb + (uint32_t)(E16_AL + r * 36 + c * 4) * 4, Qlb + (size_t)r * DIM + c * 8);
    }
    // K hi/lo: 64 n-rows x 8 chunks (16B = 4 half2), word-stride 36
    #pragma unroll
    for (int j = 0; j < 2; j++) {
        int idx = tid + j * 256;
        int r   = idx >> 3;
        int c   = idx & 7;
        cp16(sb + (uint32_t)(E16_KH + r * 36 + c * 4) * 4, Khb + (size_t)r * (DIM / 2) + c * 4);
        cp16(sb + (uint32_t)(E16_KL + r * 36 + c * 4) * 4, Klb + (size_t)r * (DIM / 2) + c * 4);
    }
    CP_COMMIT();
    CP_WAIT_0();
    __syncthreads();

    float acc[8][4];
    #pragma unroll
    for (int i = 0; i < 8; i++)
        #pragma unroll
        for (int j = 0; j < 4; j++) acc[i][j] = 0.f;

    #pragma unroll
    for (int ks = 0; ks < 4; ks++) {     // four k16 steps cover K=64
        uint32_t ah[4][4], al[4][4], bh[4], bl[4];
        #pragma unroll
        for (int mt = 0; mt < 4; mt++) {
            int r = wm + mt * 16 + a_ro;
            LDSM_X4(ah[mt], sb + (uint32_t)(E16_AH + r * 36 + ks * 8 + a_co) * 4);
            LDSM_X4(al[mt], sb + (uint32_t)(E16_AL + r * 36 + ks * 8 + a_co) * 4);
        }
        {
            int r = wn + b_ro;
            LDSM_X4(bh, sb + (uint32_t)(E16_KH + r * 36 + ks * 8 + b_co) * 4);
            LDSM_X4(bl, sb + (uint32_t)(E16_KL + r * 36 + ks * 8 + b_co) * 4);
        }
        // bh = {b[0][0], b[0][1], b[1][0], b[1][1]}
        #pragma unroll
        for (int mt = 0; mt < 4; mt++)
            #pragma unroll
            for (int nt = 0; nt < 2; nt++)
                MMA_F16(acc[mt * 2 + nt], ah[mt][0], ah[mt][1], ah[mt][2], ah[mt][3],
                        bh[nt * 2], bh[nt * 2 + 1]);
        #pragma unroll
        for (int mt = 0; mt < 4; mt++)
            #pragma unroll
            for (int nt = 0; nt < 2; nt++)
                MMA_F16(acc[mt * 2 + nt], ah[mt][0], ah[mt][1], ah[mt][2], ah[mt][3],
                        bl[nt * 2], bl[nt * 2 + 1]);
        #pragma unroll
        for (int mt = 0; mt < 4; mt++)
            #pragma unroll
            for (int nt = 0; nt < 2; nt++)
                MMA_F16(acc[mt * 2 + nt], al[mt][0], al[mt][1], al[mt][2], al[mt][3],
                        bh[nt * 2], bh[nt * 2 + 1]);
    }

    #pragma unroll
    for (int mt = 0; mt < 4; mt++) {
        int r0 = bm + wm + mt * 16 + gid;
        size_t base0 = (size_t)r0 * SEQ;
        size_t base1 = base0 + 8 * SEQ;
        #pragma unroll
        for (int nt = 0; nt < 2; nt++) {
            float* c = acc[mt * 2 + nt];
            int col = bn + wn + nt * 8 + 2 * tig;
            *(float2*)(Eb + base0 + col) = make_float2(c[0], c[1]);
            *(float2*)(Eb + base1 + col) = make_float2(c[2], c[3]);
        }
    }
}

// ===========================================================================
// softmax: in-place row softmax. fp32 probs to E + fp16 copy to P16.
// ===========================================================================
__global__ __launch_bounds__(256)
void softmax_kernel(float* __restrict__ E, __half* __restrict__ P16) {
    const int tid = threadIdx.x;
    const size_t base = (size_t)blockIdx.x * SEQ;
    float4* p = (float4*)(E + base);
    float4 v[4];
    float mx = -3.4e38f;
    #pragma unroll
    for (int i = 0; i < 4; i++) {
        v[i] = p[tid + i * 256];
        mx = fmaxf(mx, fmaxf(fmaxf(v[i].x, v[i].y), fmaxf(v[i].z, v[i].w)));
    }
    __shared__ float sred[8];
    #pragma unroll
    for (int o = 16; o > 0; o >>= 1) mx = fmaxf(mx, __shfl_xor_sync(0xffffffffu, mx, o));
    if ((tid & 31) == 0) sred[tid >> 5] = mx;
    __syncthreads();
    if (tid == 0) {
        float m = sred[0];
        #pragma unroll
        for (int i = 1; i < 8; i++) m = fmaxf(m, sred[i]);
        sred[0] = m;
    }
    __syncthreads();
    mx = sred[0];
    __syncthreads();

    float s = 0.f;
    #pragma unroll
    for (int i = 0; i < 4; i++) {
        v[i].x = __expf(v[i].x - mx);
        v[i].y = __expf(v[i].y - mx);
        v[i].z = __expf(v[i].z - mx);
        v[i].w = __expf(v[i].w - mx);
        s += (v[i].x + v[i].y) + (v[i].z + v[i].w);
    }
    #pragma unroll
    for (int o = 16; o > 0; o >>= 1) s += __shfl_xor_sync(0xffffffffu, s, o);
    if ((tid & 31) == 0) sred[tid >> 5] = s;
    __syncthreads();
    if (tid == 0) {
        float t = 0.f;
        #pragma unroll
        for (int i = 0; i < 8; i++) t += sred[i];
        sred[0] = t;
    }
    __syncthreads();
    float inv = 1.0f / sred[0];
    #pragma unroll
    for (int i = 0; i < 4; i++) {
        v[i].x *= inv; v[i].y *= inv; v[i].z *= inv; v[i].w *= inv;
        p[tid + i * 256] = v[i];
        __half2 h01 = __floats2half2_rn(v[i].x, v[i].y);
        __half2 h23 = __floats2half2_rn(v[i].z, v[i].w);
        uint2 pk;
        pk.x = *(uint32_t*)&h01;
        pk.y = *(uint32_t*)&h23;
        *(uint2*)(P16 + base + (size_t)(tid + i * 256) * 4) = pk;
    }
}

// ===========================================================================
// av_mma: Out = gamma * (Att @ V) + X on fp16 m16n8k16, ldmatrix loads.
// Block 128x128, stage K=64 (4 k16 steps), 8 warps of 64x32, 3-stage
// cp.async pipeline.
// A: fp16 probs [128 m][64 k], word-stride 36.
// B: V2T half2 [128 n][32 k2] n-major, word-stride 36.
// ===========================================================================
#define AVA_W 36
#define AVB_W 36
#define AVA_ST (128 * AVA_W)     // 4608 words
#define AVB_ST (128 * AVB_W)     // 4608 words
#define AV_NBUF 3
#define AV_SMEM_W (AV_NBUF * (AVA_ST + AVB_ST))   // 27648 words
#define AV_SMEM_BYTES (AV_SMEM_W * 4)             // 110592

__device__ __forceinline__ void av_load_stage(uint32_t sb, const __half* __restrict__ Ab,
                                              const __half2* __restrict__ Vb2T,
                                              int k0, int buf, int tid, int bn) {
    uint32_t abase = sb + buf * (AVA_ST * 4);
    #pragma unroll
    for (int j = 0; j < 4; j++) {
        int idx = tid + j * 256;     // 0..1023
        int r   = idx >> 3;          // m 0..127
        int c   = idx & 7;           // 16B chunk = 8 halves
        cp16(abase + (r * AVA_W + c * 4) * 4, Ab + (size_t)r * SEQ + k0 + c * 8);
    }
    uint32_t bbase = sb + (AV_NBUF * AVA_ST + buf * AVB_ST) * 4;
    const int k20 = k0 >> 1;
    #pragma unroll
    for (int j = 0; j < 4; j++) {
        int idx = tid + j * 256;     // 0..1023
        int r   = idx >> 3;          // ch 0..127
        int c   = idx & 7;           // 16B chunk = 4 half2
        cp16(bbase + (r * AVB_W + c * 4) * 4,
             Vb2T + (size_t)(bn + r) * (SEQ / 2) + k20 + c * 4);
    }
}

__global__ __launch_bounds__(256, 2)
void av_mma_kernel(const __half* __restrict__ P16, const __half2* __restrict__ V2T,
                   const float* __restrict__ X, const float* __restrict__ gamma,
                   float* __restrict__ Out) {
    extern __shared__ float smemf[];
    uint32_t sb = smem_u32(smemf);
    const int tid  = threadIdx.x;
    const int wid  = tid >> 5;
    const int lane = tid & 31;
    const int gid  = lane >> 2;
    const int tig  = lane & 3;
    const int wm   = (wid >> 2) * 64;
    const int wn   = (wid & 3) * 32;

    const int a_ro = ((lane >> 3) & 1) * 8 + (lane & 7);
    const int a_co = (lane >> 4) * 4;
    const int b_ro = (lane >> 4) * 8 + (lane & 7);
    const int b_co = ((lane >> 3) & 1) * 4;

    const int bz = blockIdx.z;
    const int bm = blockIdx.y * 128;
    const int bn = blockIdx.x * 128;
    const __half*  Ab   = P16 + ((size_t)bz * SEQ + bm) * SEQ;
    const __half2* Vb2T = V2T + (size_t)bz * CH * (SEQ / 2);

    float acc[16][4];
    #pragma unroll
    for (int i = 0; i < 16; i++)
        #pragma unroll
        for (int j = 0; j < 4; j++) acc[i][j] = 0.f;

    av_load_stage(sb, Ab, Vb2T, 0,   0, tid, bn); CP_COMMIT();
    av_load_stage(sb, Ab, Vb2T, 64,  1, tid, bn); CP_COMMIT();
    av_load_stage(sb, Ab, Vb2T, 128, 2, tid, bn); CP_COMMIT();

    const int NS = SEQ / 64;   // 64
    for (int s = 0; s < NS; s++) {
        const int buf = s % 3;
        if (s + 2 < NS)      { CP_WAIT_2(); }
        else if (s + 1 < NS) { CP_WAIT_1(); }
        else                 { CP_WAIT_0(); }
        __syncthreads();

        uint32_t abase = sb + buf * (AVA_ST * 4);
        uint32_t bbase = sb + (AV_NBUF * AVA_ST + buf * AVB_ST) * 4;

        #pragma unroll
        for (int ks = 0; ks < 4; ks++) {      // four k16 steps cover K=64
            uint32_t a[4][4], b0[4], b1[4];
            #pragma unroll
            for (int mt = 0; mt < 4; mt++) {
                int r = wm + mt * 16 + a_ro;
                LDSM_X4(a[mt], abase + (uint32_t)(r * AVA_W + ks * 8 + a_co) * 4);
            }
            {
                int r = wn + b_ro;
                LDSM_X4(b0, bbase + (uint32_t)(r * AVB_W + ks * 8 + b_co) * 4);
                LDSM_X4(b1, bbase + (uint32_t)((r + 16) * AVB_W + ks * 8 + b_co) * 4);
            }
            // b0 = {b[0][0], b[0][1], b[1][0], b[1][1]}  (nt 0,1)
            // b1 = same for nt 2,3
            #pragma unroll
            for (int mt = 0; mt < 4; mt++) {
                MMA_F16(acc[mt * 4 + 0], a[mt][0], a[mt][1], a[mt][2], a[mt][3], b0[0], b0[1]);
                MMA_F16(acc[mt * 4 + 1], a[mt][0], a[mt][1], a[mt][2], a[mt][3], b0[2], b0[3]);
                MMA_F16(acc[mt * 4 + 2], a[mt][0], a[mt][1], a[mt][2], a[mt][3], b1[0], b1[1]);
                MMA_F16(acc[mt * 4 + 3], a[mt][0], a[mt][1], a[mt][2], a[mt][3], b1[2], b1[3]);
            }
        }
        __syncthreads();
        if (s + 3 < NS) {
            av_load_stage(sb, Ab, Vb2T, (s + 3) * 64, buf, tid, bn);
            CP_COMMIT();
        }
    }

    const float g = gamma[0];
    #pragma unroll
    for (int mt = 0; mt < 4; mt++) {
        int r0 = bm + wm + mt * 16 + gid;
        size_t base0 = ((size_t)bz * SEQ + r0) * CH;
        size_t base1 = base0 + 8 * CH;
        #pragma unroll
        for (int nt = 0; nt < 4; nt++) {
            float* c = acc[mt * 4 + nt];
            int col = bn + wn + nt * 8 + 2 * tig;
            float2 x0 = *(const float2*)(X + base0 + col);
            float2 x1 = *(const float2*)(X + base1 + col);
            float2 o0, o1;
            o0.x = fmaf(g, c[0], x0.x); o0.y = fmaf(g, c[1], x0.y);
            o1.x = fmaf(g, c[2], x1.x); o1.y = fmaf(g, c[3], x1.y);
            *(float2*)(Out + base0 + col) = o0;
            *(float2*)(Out + base1 + col) = o1;
        }
    }
}

// ===========================================================================
extern "C" void kernel_launch(void* const* d_in, const int* in_sizes, int n_in,
                              void* d_out, int out_size) {
    const float* x     = (const float*)d_in[0];
    const float* Wq    = (const float*)d_in[1];
    const float* bq    = (const float*)d_in[2];
    const float* Wk    = (const float*)d_in[3];
    const float* bk    = (const float*)d_in[4];
    const float* Wv    = (const float*)d_in[5];
    const float* bv    = (const float*)d_in[6];
    const float* gamma = (const float*)d_in[7];

    float* out = (float*)d_out;                              // [B, N, C]
    float* att = out + (size_t)BATCH * SEQ * CH;             // [B, N, N]

    __half *qh16, *ql16, *p16;
    float *v;
    __half2 *kh2, *kl2, *v2T;
    cudaGetSymbolAddress((void**)&qh16, g_qh16);
    cudaGetSymbolAddress((void**)&ql16, g_ql16);
    cudaGetSymbolAddress((void**)&kh2,  g_kh2);
    cudaGetSymbolAddress((void**)&kl2,  g_kl2);
    cudaGetSymbolAddress((void**)&v,    g_v);
    cudaGetSymbolAddress((void**)&v2T,  g_v2T);
    cudaGetSymbolAddress((void**)&p16,  g_p16);

    static bool attr_set = false;
    if (!attr_set) {
        cudaFuncSetAttribute(av_mma_kernel, cudaFuncAttributeMaxDynamicSharedMemorySize, AV_SMEM_BYTES);
        cudaFuncSetAttribute(energy_mma_kernel, cudaFuncAttributeMaxDynamicSharedMemorySize, E16_SMEM_BYTES);
        attr_set = true;
    }

    const int M = BATCH * SEQ;  // 65536

    // Projections: q fp16 hi/lo planes; k fp16 hi/lo pair-interleaved [n][d2]; v fp32
    proj_kernel<<<dim3(DIM / 64, M / 128), 256>>>(x, Wq, bq, nullptr, qh16, ql16, nullptr, nullptr, DIM, 1);
    proj_kernel<<<dim3(DIM / 64, M / 128), 256>>>(x, Wk, bk, nullptr, nullptr, nullptr, kh2, kl2, DIM, 3);
    proj_kernel<<<dim3(CH  / 64, M / 128), 256>>>(x, Wv, bv, v, nullptr, nullptr, nullptr, nullptr, CH, 0);

    // v -> v2T fp16 pair-interleaved [ch][seq2]
    vsplit_kernel<<<dim3(CH / 32, SEQ / 32, BATCH), 256>>>(v, v2T);

    // Logits on fp16 tensor cores (Dekker hh+hl+lh), ldmatrix operand loads
    energy_mma_kernel<<<dim3(SEQ / 64, SEQ / 128, BATCH), 256, E16_SMEM_BYTES>>>(qh16, ql16, kh2, kl2, att);

    // Row softmax: fp32 probs (checked output) + fp16 copy for AV
    softmax_kernel<<<M, 256>>>(att, p16);

    // attn @ V on fp16 tensor cores, ldmatrix operand loads, fused gamma-residual
    av_mma_kernel<<<dim3(CH / 128, SEQ / 128, BATCH), 256, AV_SMEM_BYTES>>>(p16, v2T, x, gamma, out);
}

// round 16
// speedup vs baseline: 1.4569x; 1.0343x over previous
#include <cuda_runtime.h>
#include <cuda_fp16.h>
#include <cstdint>

#define BATCH 16
#define SEQ   4096
#define CH    512
#define DIM   64

// Scratch (allocation-free per harness rules)
__device__ __half  g_qh16[BATCH * SEQ * DIM];             // q hi fp16 [m][d] flat
__device__ __half  g_ql16[BATCH * SEQ * DIM];             // q lo fp16
__device__ __half2 g_kh2[BATCH * SEQ * (DIM / 2)];        // k hi pair-interleaved [m][d2]
__device__ __half2 g_kl2[BATCH * SEQ * (DIM / 2)];        // k lo
__device__ __half2 g_v2T[BATCH * CH * (SEQ / 2)];         // v fp16 pair-interleaved [b][ch][seq2]
__device__ __half  g_p16[(size_t)BATCH * SEQ * SEQ];      // fp16 probs copy

// ===========================================================================
// helpers
// ===========================================================================
__device__ __forceinline__ uint32_t smem_u32(const void* p) {
    uint32_t a;
    asm("{ .reg .u64 t; cvta.to.shared.u64 t, %1; cvt.u32.u64 %0, t; }" : "=r"(a) : "l"(p));
    return a;
}
__device__ __forceinline__ void cp16(uint32_t dst, const void* src) {
    asm volatile("cp.async.cg.shared.global [%0], [%1], 16;" :: "r"(dst), "l"(src));
}
#define CP_COMMIT() asm volatile("cp.async.commit_group;" ::: "memory")
#define CP_WAIT_2() asm volatile("cp.async.wait_group 2;" ::: "memory")
#define CP_WAIT_1() asm volatile("cp.async.wait_group 1;" ::: "memory")
#define CP_WAIT_0() asm volatile("cp.async.wait_group 0;" ::: "memory")

#define MMA_F16(c, a0, a1, a2, a3, b0, b1) \
    asm volatile( \
        "mma.sync.aligned.m16n8k16.row.col.f32.f16.f16.f32 " \
        "{%0,%1,%2,%3}, {%4,%5,%6,%7}, {%8,%9}, {%0,%1,%2,%3};" \
        : "+f"((c)[0]), "+f"((c)[1]), "+f"((c)[2]), "+f"((c)[3]) \
        : "r"(a0), "r"(a1), "r"(a2), "r"(a3), "r"(b0), "r"(b1))

#define LDSM_X4(r, addr) \
    asm volatile("ldmatrix.sync.aligned.m8n8.x4.shared.b16 {%0,%1,%2,%3}, [%4];" \
        : "=r"((r)[0]), "=r"((r)[1]), "=r"((r)[2]), "=r"((r)[3]) : "r"(addr))

// ===========================================================================
// projqk: q and k projections fused — one pass over x.
// q -> fp16 hi/lo planes [m][64];  k -> fp16 hi/lo pair-interleaved [m][32] half2.
// Tile 128m x 64n (N=DIM=64), K=512 in 32-chunks.
// ===========================================================================
__global__ __launch_bounds__(256, 2)
void projqk_kernel(const float* __restrict__ A,
                   const float* __restrict__ Wq, const float* __restrict__ bq,
                   const float* __restrict__ Wk, const float* __restrict__ bk,
                   __half* __restrict__ Qh, __half* __restrict__ Ql,
                   __half2* __restrict__ Kh2, __half2* __restrict__ Kl2) {
    const int K = CH;
    const int N = DIM;
    __shared__ float As[32][132];
    __shared__ float Wqs[32][64];
    __shared__ float Wks[32][64];
    const int bm = blockIdx.x * 128;
    const int tid = threadIdx.x;
    const int tn = tid & 15;
    const int tm = tid >> 4;
    float accq[8][4] = {};
    float acck[8][4] = {};

    for (int k0 = 0; k0 < K; k0 += 32) {
        #pragma unroll
        for (int i = 0; i < 4; i++) {
            int fidx = tid + i * 256;
            int row  = fidx >> 3;
            int kc   = (fidx & 7) * 4;
            float4 t = *(const float4*)(A + (size_t)(bm + row) * K + k0 + kc);
            As[kc + 0][row] = t.x; As[kc + 1][row] = t.y;
            As[kc + 2][row] = t.z; As[kc + 3][row] = t.w;
        }
        #pragma unroll
        for (int i = 0; i < 2; i++) {
            int fidx = tid + i * 256;
            int kr   = fidx >> 4;
            int nc   = (fidx & 15) * 4;
            *(float4*)&Wqs[kr][nc] = *(const float4*)(Wq + (size_t)(k0 + kr) * N + nc);
            *(float4*)&Wks[kr][nc] = *(const float4*)(Wk + (size_t)(k0 + kr) * N + nc);
        }
        __syncthreads();
        #pragma unroll
        for (int kk = 0; kk < 32; kk++) {
            float4 a0 = *(const float4*)&As[kk][tm * 8];
            float4 a1 = *(const float4*)&As[kk][tm * 8 + 4];
            float4 wq0 = *(const float4*)&Wqs[kk][tn * 4];
            float4 wk0 = *(const float4*)&Wks[kk][tn * 4];
            float a[8] = {a0.x, a0.y, a0.z, a0.w, a1.x, a1.y, a1.z, a1.w};
            float wq[4] = {wq0.x, wq0.y, wq0.z, wq0.w};
            float wk[4] = {wk0.x, wk0.y, wk0.z, wk0.w};
            #pragma unroll
            for (int i = 0; i < 8; i++) {
                #pragma unroll
                for (int j = 0; j < 4; j++) {
                    accq[i][j] = fmaf(a[i], wq[j], accq[i][j]);
                    acck[i][j] = fmaf(a[i], wk[j], acck[i][j]);
                }
            }
        }
        __syncthreads();
    }
    const int N2 = N >> 1;
    #pragma unroll
    for (int i = 0; i < 8; i++) {
        size_t row = bm + tm * 8 + i;
        int col = tn * 4;
        // q: hi/lo planes
        {
            float v0 = accq[i][0] + bq[col + 0];
            float v1 = accq[i][1] + bq[col + 1];
            float v2 = accq[i][2] + bq[col + 2];
            float v3 = accq[i][3] + bq[col + 3];
            __half h0 = __float2half_rn(v0), h1 = __float2half_rn(v1);
            __half h2 = __float2half_rn(v2), h3 = __float2half_rn(v3);
            __half l0 = __float2half_rn(v0 - __half2float(h0));
            __half l1 = __float2half_rn(v1 - __half2float(h1));
            __half l2 = __float2half_rn(v2 - __half2float(h2));
            __half l3 = __float2half_rn(v3 - __half2float(h3));
            __half2* ph = (__half2*)(Qh + row * N + col);
            __half2* pl = (__half2*)(Ql + row * N + col);
            ph[0] = __halves2half2(h0, h1); ph[1] = __halves2half2(h2, h3);
            pl[0] = __halves2half2(l0, l1); pl[1] = __halves2half2(l2, l3);
        }
        // k: hi/lo pair-interleaved along d
        {
            float v0 = acck[i][0] + bk[col + 0];
            float v1 = acck[i][1] + bk[col + 1];
            float v2 = acck[i][2] + bk[col + 2];
            float v3 = acck[i][3] + bk[col + 3];
            __half h0 = __float2half_rn(v0), h1 = __float2half_rn(v1);
            __half h2 = __float2half_rn(v2), h3 = __float2half_rn(v3);
            __half l0 = __float2half_rn(v0 - __half2float(h0));
            __half l1 = __float2half_rn(v1 - __half2float(h1));
            __half l2 = __float2half_rn(v2 - __half2float(h2));
            __half l3 = __float2half_rn(v3 - __half2float(h3));
            size_t off = row * N2 + (col >> 1);
            Kh2[off]     = __halves2half2(h0, h1);
            Kh2[off + 1] = __halves2half2(h2, h3);
            Kl2[off]     = __halves2half2(l0, l1);
            Kl2[off + 1] = __halves2half2(l2, l3);
        }
    }
}

// ===========================================================================
// projv: v projection, emits v2T [b][ch][seq2] half2 directly (smem-transposed
// epilogue) — no fp32 v round-trip, no separate vsplit kernel.
// Tile 128m x 64ch, K=512.
// ===========================================================================
#define PV_POOL (64 * 129)       // 8256 floats: epilogue transpose buffer

__global__ __launch_bounds__(256, 2)
void projv_kernel(const float* __restrict__ A, const float* __restrict__ W,
                  const float* __restrict__ bias, __half2* __restrict__ V2T) {
    const int K = CH;
    const int N = CH;
    __shared__ float pool[PV_POOL];
    float (*As)[132] = (float (*)[132])pool;              // [32][132] = 4224
    float (*Ws)[64]  = (float (*)[64])(pool + 4224);      // [32][64]  = 2048
    const int bm = blockIdx.y * 128;
    const int bn = blockIdx.x * 64;
    const int tid = threadIdx.x;
    const int tn = tid & 15;
    const int tm = tid >> 4;
    float acc[8][4] = {};

    for (int k0 = 0; k0 < K; k0 += 32) {
        #pragma unroll
        for (int i = 0; i < 4; i++) {
            int fidx = tid + i * 256;
            int row  = fidx >> 3;
            int kc   = (fidx & 7) * 4;
            float4 t = *(const float4*)(A + (size_t)(bm + row) * K + k0 + kc);
            As[kc + 0][row] = t.x; As[kc + 1][row] = t.y;
            As[kc + 2][row] = t.z; As[kc + 3][row] = t.w;
        }
        #pragma unroll
        for (int i = 0; i < 2; i++) {
            int fidx = tid + i * 256;
            int kr   = fidx >> 4;
            int nc   = (fidx & 15) * 4;
            *(float4*)&Ws[kr][nc] = *(const float4*)(W + (size_t)(k0 + kr) * N + bn + nc);
        }
        __syncthreads();
        #pragma unroll
        for (int kk = 0; kk < 32; kk++) {
            float4 a0 = *(const float4*)&As[kk][tm * 8];
            float4 a1 = *(const float4*)&As[kk][tm * 8 + 4];
            float4 w0 = *(const float4*)&Ws[kk][tn * 4];
            float a[8] = {a0.x, a0.y, a0.z, a0.w, a1.x, a1.y, a1.z, a1.w};
            float w[4] = {w0.x, w0.y, w0.z, w0.w};
            #pragma unroll
            for (int i = 0; i < 8; i++)
                #pragma unroll
                for (int j = 0; j < 4; j++)
                    acc[i][j] = fmaf(a[i], w[j], acc[i][j]);
        }
        __syncthreads();
    }

    // epilogue: stage fp32 tile transposed in smem: S[ch 64][m 128], stride 129
    #pragma unroll
    for (int i = 0; i < 8; i++) {
        int m = tm * 8 + i;
        #pragma unroll
        for (int j = 0; j < 4; j++) {
            int n = tn * 4 + j;
            pool[n * 129 + m] = acc[i][j] + bias[bn + n];
        }
    }
    __syncthreads();

    // emit pair-interleaved half2: v2T[b][bn+ch][tok0/2 + m2]
    const int b    = bm >> 12;               // bm / SEQ
    const int tok0 = bm & (SEQ - 1);
    __half2* Tb = V2T + ((size_t)b * CH + bn) * (SEQ / 2) + (tok0 >> 1);
    #pragma unroll
    for (int t = 0; t < 16; t++) {
        int idx = tid + t * 256;             // 0..4095
        int ch  = idx >> 6;                  // 0..63
        int m2  = idx & 63;                  // 0..63
        float v0 = pool[ch * 129 + 2 * m2];
        float v1 = pool[ch * 129 + 2 * m2 + 1];
        Tb[(size_t)ch * (SEQ / 2) + m2] = __floats2half2_rn(v0, v1);
    }
}

// ===========================================================================
// energy_mma: E = QK^T on fp16 m16n8k16 (Dekker hh+hl+lh), ldmatrix loads.
// 128m x 64n tile, K=64 whole reduction, 8 warps of 64m x 16n, 2 CTAs/SM.
// ===========================================================================
#define E16_AH 0
#define E16_AL 4608                      // 128*36
#define E16_KH 9216
#define E16_KL 11520                     // +64*36
#define E16_SMEM_W 13824
#define E16_SMEM_BYTES (E16_SMEM_W * 4)  // 55296

__global__ __launch_bounds__(256, 2)
void energy_mma_kernel(const __half* __restrict__ Qh, const __half* __restrict__ Ql,
                       const __half2* __restrict__ Kh2, const __half2* __restrict__ Kl2,
                       float* __restrict__ E) {
    extern __shared__ float smemf[];
    uint32_t sb = smem_u32(smemf);

    const int tid  = threadIdx.x;
    const int wid  = tid >> 5;
    const int lane = tid & 31;
    const int gid  = lane >> 2;
    const int tig  = lane & 3;
    const int wm   = (wid >> 2) * 64;    // 0 or 64
    const int wn   = (wid & 3) * 16;     // 0,16,32,48

    const int a_ro = ((lane >> 3) & 1) * 8 + (lane & 7);
    const int a_co = (lane >> 4) * 4;
    const int b_ro = (lane >> 4) * 8 + (lane & 7);
    const int b_co = ((lane >> 3) & 1) * 4;

    const int bz = blockIdx.z;
    const int bm = blockIdx.y * 128;
    const int bn = blockIdx.x * 64;
    const __half* Qhb = Qh + ((size_t)bz * SEQ + bm) * DIM;
    const __half* Qlb = Ql + ((size_t)bz * SEQ + bm) * DIM;
    const __half2* Khb = Kh2 + ((size_t)bz * SEQ + bn) * (DIM / 2);
    const __half2* Klb = Kl2 + ((size_t)bz * SEQ + bn) * (DIM / 2);
    float* Eb = E + (size_t)bz * SEQ * SEQ;

    #pragma unroll
    for (int j = 0; j < 4; j++) {
        int idx = tid + j * 256;
        int r   = idx >> 3;
        int c   = idx & 7;
        cp16(sb + (uint32_t)(E16_AH + r * 36 + c * 4) * 4, Qhb + (size_t)r * DIM + c * 8);
        cp16(sb + (uint32_t)(E16_AL + r * 36 + c * 4) * 4, Qlb + (size_t)r * DIM + c * 8);
    }
    #pragma unroll
    for (int j = 0; j < 2; j++) {
        int idx = tid + j * 256;
        int r   = idx >> 3;
        int c   = idx & 7;
        cp16(sb + (uint32_t)(E16_KH + r * 36 + c * 4) * 4, Khb + (size_t)r * (DIM / 2) + c * 4);
        cp16(sb + (uint32_t)(E16_KL + r * 36 + c * 4) * 4, Klb + (size_t)r * (DIM / 2) + c * 4);
    }
    CP_COMMIT();
    CP_WAIT_0();
    __syncthreads();

    float acc[8][4];
    #pragma unroll
    for (int i = 0; i < 8; i++)
        #pragma unroll
        for (int j = 0; j < 4; j++) acc[i][j] = 0.f;

    #pragma unroll
    for (int ks = 0; ks < 4; ks++) {
        uint32_t ah[4][4], al[4][4], bh[4], bl[4];
        #pragma unroll
        for (int mt = 0; mt < 4; mt++) {
            int r = wm + mt * 16 + a_ro;
            LDSM_X4(ah[mt], sb + (uint32_t)(E16_AH + r * 36 + ks * 8 + a_co) * 4);
            LDSM_X4(al[mt], sb + (uint32_t)(E16_AL + r * 36 + ks * 8 + a_co) * 4);
        }
        {
            int r = wn + b_ro;
            LDSM_X4(bh, sb + (uint32_t)(E16_KH + r * 36 + ks * 8 + b_co) * 4);
            LDSM_X4(bl, sb + (uint32_t)(E16_KL + r * 36 + ks * 8 + b_co) * 4);
        }
        #pragma unroll
        for (int mt = 0; mt < 4; mt++)
            #pragma unroll
            for (int nt = 0; nt < 2; nt++)
                MMA_F16(acc[mt * 2 + nt], ah[mt][0], ah[mt][1], ah[mt][2], ah[mt][3],
                        bh[nt * 2], bh[nt * 2 + 1]);
        #pragma unroll
        for (int mt = 0; mt < 4; mt++)
            #pragma unroll
            for (int nt = 0; nt < 2; nt++)
                MMA_F16(acc[mt * 2 + nt], ah[mt][0], ah[mt][1], ah[mt][2], ah[mt][3],
                        bl[nt * 2], bl[nt * 2 + 1]);
        #pragma unroll
        for (int mt = 0; mt < 4; mt++)
            #pragma unroll
            for (int nt = 0; nt < 2; nt++)
                MMA_F16(acc[mt * 2 + nt], al[mt][0], al[mt][1], al[mt][2], al[mt][3],
                        bh[nt * 2], bh[nt * 2 + 1]);
    }

    #pragma unroll
    for (int mt = 0; mt < 4; mt++) {
        int r0 = bm + wm + mt * 16 + gid;
        size_t base0 = (size_t)r0 * SEQ;
        size_t base1 = base0 + 8 * SEQ;
        #pragma unroll
        for (int nt = 0; nt < 2; nt++) {
            float* c = acc[mt * 2 + nt];
            int col = bn + wn + nt * 8 + 2 * tig;
            *(float2*)(Eb + base0 + col) = make_float2(c[0], c[1]);
            *(float2*)(Eb + base1 + col) = make_float2(c[2], c[3]);
        }
    }
}

// ===========================================================================
// softmax: in-place row softmax. fp32 probs to E + fp16 copy to P16.
// ===========================================================================
__global__ __launch_bounds__(256)
void softmax_kernel(float* __restrict__ E, __half* __restrict__ P16) {
    const int tid = threadIdx.x;
    const size_t base = (size_t)blockIdx.x * SEQ;
    float4* p = (float4*)(E + base);
    float4 v[4];
    float mx = -3.4e38f;
    #pragma unroll
    for (int i = 0; i < 4; i++) {
        v[i] = p[tid + i * 256];
        mx = fmaxf(mx, fmaxf(fmaxf(v[i].x, v[i].y), fmaxf(v[i].z, v[i].w)));
    }
    __shared__ float sred[8];
    #pragma unroll
    for (int o = 16; o > 0; o >>= 1) mx = fmaxf(mx, __shfl_xor_sync(0xffffffffu, mx, o));
    if ((tid & 31) == 0) sred[tid >> 5] = mx;
    __syncthreads();
    if (tid == 0) {
        float m = sred[0];
        #pragma unroll
        for (int i = 1; i < 8; i++) m = fmaxf(m, sred[i]);
        sred[0] = m;
    }
    __syncthreads();
    mx = sred[0];
    __syncthreads();

    float s = 0.f;
    #pragma unroll
    for (int i = 0; i < 4; i++) {
        v[i].x = __expf(v[i].x - mx);
        v[i].y = __expf(v[i].y - mx);
        v[i].z = __expf(v[i].z - mx);
        v[i].w = __expf(v[i].w - mx);
        s += (v[i].x + v[i].y) + (v[i].z + v[i].w);
    }
    #pragma unroll
    for (int o = 16; o > 0; o >>= 1) s += __shfl_xor_sync(0xffffffffu, s, o);
    if ((tid & 31) == 0) sred[tid >> 5] = s;
    __syncthreads();
    if (tid == 0) {
        float t = 0.f;
        #pragma unroll
        for (int i = 0; i < 8; i++) t += sred[i];
        sred[0] = t;
    }
    __syncthreads();
    float inv = 1.0f / sred[0];
    #pragma unroll
    for (int i = 0; i < 4; i++) {
        v[i].x *= inv; v[i].y *= inv; v[i].z *= inv; v[i].w *= inv;
        p[tid + i * 256] = v[i];
        __half2 h01 = __floats2half2_rn(v[i].x, v[i].y);
        __half2 h23 = __floats2half2_rn(v[i].z, v[i].w);
        uint2 pk;
        pk.x = *(uint32_t*)&h01;
        pk.y = *(uint32_t*)&h23;
        *(uint2*)(P16 + base + (size_t)(tid + i * 256) * 4) = pk;
    }
}

// ===========================================================================
// av_mma: Out = gamma * (Att @ V) + X on fp16 m16n8k16, ldmatrix loads.
// Block 128x128, stage K=64 (4 k16 steps), 8 warps of 64x32, 3-stage
// cp.async pipeline.
// ===========================================================================
#define AVA_W 36
#define AVB_W 36
#define AVA_ST (128 * AVA_W)     // 4608 words
#define AVB_ST (128 * AVB_W)     // 4608 words
#define AV_NBUF 3
#define AV_SMEM_W (AV_NBUF * (AVA_ST + AVB_ST))   // 27648 words
#define AV_SMEM_BYTES (AV_SMEM_W * 4)             // 110592

__device__ __forceinline__ void av_load_stage(uint32_t sb, const __half* __restrict__ Ab,
                                              const __half2* __restrict__ Vb2T,
                                              int k0, int buf, int tid, int bn) {
    uint32_t abase = sb + buf * (AVA_ST * 4);
    #pragma unroll
    for (int j = 0; j < 4; j++) {
        int idx = tid + j * 256;
        int r   = idx >> 3;
        int c   = idx & 7;
        cp16(abase + (r * AVA_W + c * 4) * 4, Ab + (size_t)r * SEQ + k0 + c * 8);
    }
    uint32_t bbase = sb + (AV_NBUF * AVA_ST + buf * AVB_ST) * 4;
    const int k20 = k0 >> 1;
    #pragma unroll
    for (int j = 0; j < 4; j++) {
        int idx = tid + j * 256;
        int r   = idx >> 3;
        int c   = idx & 7;
        cp16(bbase + (r * AVB_W + c * 4) * 4,
             Vb2T + (size_t)(bn + r) * (SEQ / 2) + k20 + c * 4);
    }
}

__global__ __launch_bounds__(256, 2)
void av_mma_kernel(const __half* __restrict__ P16, const __half2* __restrict__ V2T,
                   const float* __restrict__ X, const float* __restrict__ gamma,
                   float* __restrict__ Out) {
    extern __shared__ float smemf[];
    uint32_t sb = smem_u32(smemf);
    const int tid  = threadIdx.x;
    const int wid  = tid >> 5;
    const int lane = tid & 31;
    const int gid  = lane >> 2;
    const int tig  = lane & 3;
    const int wm   = (wid >> 2) * 64;
    const int wn   = (wid & 3) * 32;

    const int a_ro = ((lane >> 3) & 1) * 8 + (lane & 7);
    const int a_co = (lane >> 4) * 4;
    const int b_ro = (lane >> 4) * 8 + (lane & 7);
    const int b_co = ((lane >> 3) & 1) * 4;

    const int bz = blockIdx.z;
    const int bm = blockIdx.y * 128;
    const int bn = blockIdx.x * 128;
    const __half*  Ab   = P16 + ((size_t)bz * SEQ + bm) * SEQ;
    const __half2* Vb2T = V2T + (size_t)bz * CH * (SEQ / 2);

    float acc[16][4];
    #pragma unroll
    for (int i = 0; i < 16; i++)
        #pragma unroll
        for (int j = 0; j < 4; j++) acc[i][j] = 0.f;

    av_load_stage(sb, Ab, Vb2T, 0,   0, tid, bn); CP_COMMIT();
    av_load_stage(sb, Ab, Vb2T, 64,  1, tid, bn); CP_COMMIT();
    av_load_stage(sb, Ab, Vb2T, 128, 2, tid, bn); CP_COMMIT();

    const int NS = SEQ / 64;   // 64
    for (int s = 0; s < NS; s++) {
        const int buf = s % 3;
        if (s + 2 < NS)      { CP_WAIT_2(); }
        else if (s + 1 < NS) { CP_WAIT_1(); }
        else                 { CP_WAIT_0(); }
        __syncthreads();

        uint32_t abase = sb + buf * (AVA_ST * 4);
        uint32_t bbase = sb + (AV_NBUF * AVA_ST + buf * AVB_ST) * 4;

        #pragma unroll
        for (int ks = 0; ks < 4; ks++) {
            uint32_t a[4][4], b0[4], b1[4];
            #pragma unroll
            for (int mt = 0; mt < 4; mt++) {
                int r = wm + mt * 16 + a_ro;
                LDSM_X4(a[mt], abase + (uint32_t)(r * AVA_W + ks * 8 + a_co) * 4);
            }
            {
                int r = wn + b_ro;
                LDSM_X4(b0, bbase + (uint32_t)(r * AVB_W + ks * 8 + b_co) * 4);
                LDSM_X4(b1, bbase + (uint32_t)((r + 16) * AVB_W + ks * 8 + b_co) * 4);
            }
            #pragma unroll
            for (int mt = 0; mt < 4; mt++) {
                MMA_F16(acc[mt * 4 + 0], a[mt][0], a[mt][1], a[mt][2], a[mt][3], b0[0], b0[1]);
                MMA_F16(acc[mt * 4 + 1], a[mt][0], a[mt][1], a[mt][2], a[mt][3], b0[2], b0[3]);
                MMA_F16(acc[mt * 4 + 2], a[mt][0], a[mt][1], a[mt][2], a[mt][3], b1[0], b1[1]);
                MMA_F16(acc[mt * 4 + 3], a[mt][0], a[mt][1], a[mt][2], a[mt][3], b1[2], b1[3]);
            }
        }
        __syncthreads();
        if (s + 3 < NS) {
            av_load_stage(sb, Ab, Vb2T, (s + 3) * 64, buf, tid, bn);
            CP_COMMIT();
        }
    }

    const float g = gamma[0];
    #pragma unroll
    for (int mt = 0; mt < 4; mt++) {
        int r0 = bm + wm + mt * 16 + gid;
        size_t base0 = ((size_t)bz * SEQ + r0) * CH;
        size_t base1 = base0 + 8 * CH;
        #pragma unroll
        for (int nt = 0; nt < 4; nt++) {
            float* c = acc[mt * 4 + nt];
            int col = bn + wn + nt * 8 + 2 * tig;
            float2 x0 = *(const float2*)(X + base0 + col);
            float2 x1 = *(const float2*)(X + base1 + col);
            float2 o0, o1;
            o0.x = fmaf(g, c[0], x0.x); o0.y = fmaf(g, c[1], x0.y);
            o1.x = fmaf(g, c[2], x1.x); o1.y = fmaf(g, c[3], x1.y);
            *(float2*)(Out + base0 + col) = o0;
            *(float2*)(Out + base1 + col) = o1;
        }
    }
}

// ===========================================================================
extern "C" void kernel_launch(void* const* d_in, const int* in_sizes, int n_in,
                              void* d_out, int out_size) {
    const float* x     = (const float*)d_in[0];
    const float* Wq    = (const float*)d_in[1];
    const float* bq    = (const float*)d_in[2];
    const float* Wk    = (const float*)d_in[3];
    const float* bk    = (const float*)d_in[4];
    const float* Wv    = (const float*)d_in[5];
    const float* bv    = (const float*)d_in[6];
    const float* gamma = (const float*)d_in[7];

    float* out = (float*)d_out;                              // [B, N, C]
    float* att = out + (size_t)BATCH * SEQ * CH;             // [B, N, N]

    __half *qh16, *ql16, *p16;
    __half2 *kh2, *kl2, *v2T;
    cudaGetSymbolAddress((void**)&qh16, g_qh16);
    cudaGetSymbolAddress((void**)&ql16, g_ql16);
    cudaGetSymbolAddress((void**)&kh2,  g_kh2);
    cudaGetSymbolAddress((void**)&kl2,  g_kl2);
    cudaGetSymbolAddress((void**)&v2T,  g_v2T);
    cudaGetSymbolAddress((void**)&p16,  g_p16);

    static bool attr_set = false;
    if (!attr_set) {
        cudaFuncSetAttribute(av_mma_kernel, cudaFuncAttributeMaxDynamicSharedMemorySize, AV_SMEM_BYTES);
        cudaFuncSetAttribute(energy_mma_kernel, cudaFuncAttributeMaxDynamicSharedMemorySize, E16_SMEM_BYTES);
        attr_set = true;
    }

    const int M = BATCH * SEQ;  // 65536

    // q + k fused projection (single x pass); v projection emits v2T directly
    projqk_kernel<<<M / 128, 256>>>(x, Wq, bq, Wk, bk, qh16, ql16, kh2, kl2);
    projv_kernel<<<dim3(CH / 64, M / 128), 256>>>(x, Wv, bv, v2T);

    // Logits on fp16 tensor cores (Dekker hh+hl+lh), ldmatrix operand loads
    energy_mma_kernel<<<dim3(SEQ / 64, SEQ / 128, BATCH), 256, E16_SMEM_BYTES>>>(qh16, ql16, kh2, kl2, att);

    // Row softmax: fp32 probs (checked output) + fp16 copy for AV
    softmax_kernel<<<M, 256>>>(att, p16);

    // attn @ V on fp16 tensor cores, ldmatrix operand loads, fused gamma-residual
    av_mma_kernel<<<dim3(CH / 128, SEQ / 128, BATCH), 256, AV_SMEM_BYTES>>>(p16, v2T, x, gamma, out);
}